// round 1
// baseline (speedup 1.0000x reference)
#include <cuda_runtime.h>
#include <math.h>

// Problem constants
#define BATCH 2
#define SEQ   2048
#define HEADS 16
#define DK    64
#define DM    1024
#define MROWS (BATCH * SEQ)   // 4096

// Scratch (device globals — no allocation allowed)
__device__ float g_Q[BATCH * HEADS * SEQ * DK];   // [B,H,T,dk]
__device__ float g_K[BATCH * HEADS * SEQ * DK];
__device__ float g_V[BATCH * HEADS * SEQ * DK];
__device__ float g_ctx[BATCH * SEQ * DM];          // [B,T,DM]

// ---------------------------------------------------------------------------
// GEMM: Y = X @ W^T + bias.  X:[M,K] row-major, W:[N,K] row-major.
// MODE 0: Y[m*N + n]   (plain [M,N])
// MODE 1: scatter to [B,H,T,dk] layout (for Q/K/V projections)
// BM=BN=64, BK=16, 256 threads, 4x4 register micro-tile per thread.
// M,N multiples of 64; K multiple of 16 (true here: 4096/1024/1024).
// ---------------------------------------------------------------------------
template <int MODE>
__global__ void gemm_bias_kernel(const float* __restrict__ X,
                                 const float* __restrict__ W,
                                 const float* __restrict__ bias,
                                 float* __restrict__ Y,
                                 int M, int N, int K)
{
    const int BM = 64, BN = 64, BK = 16;
    __shared__ float Xs[BK][BM + 4];
    __shared__ float Ws[BK][BN + 4];

    const int tid = threadIdx.x;        // 0..255
    const int tx = tid & 15;            // 0..15
    const int ty = tid >> 4;            // 0..15
    const int m0 = blockIdx.y * BM;
    const int n0 = blockIdx.x * BN;

    float acc[4][4];
#pragma unroll
    for (int i = 0; i < 4; i++)
#pragma unroll
        for (int j = 0; j < 4; j++) acc[i][j] = 0.f;

    for (int k0 = 0; k0 < K; k0 += BK) {
        // Load 64x16 tiles of X and W (one float4 per thread each), transpose into smem
        {
            const int r  = tid >> 2;         // 0..63
            const int c4 = (tid & 3) << 2;   // 0,4,8,12
            float4 vx = *reinterpret_cast<const float4*>(&X[(size_t)(m0 + r) * K + k0 + c4]);
            Xs[c4 + 0][r] = vx.x; Xs[c4 + 1][r] = vx.y;
            Xs[c4 + 2][r] = vx.z; Xs[c4 + 3][r] = vx.w;
            float4 vw = *reinterpret_cast<const float4*>(&W[(size_t)(n0 + r) * K + k0 + c4]);
            Ws[c4 + 0][r] = vw.x; Ws[c4 + 1][r] = vw.y;
            Ws[c4 + 2][r] = vw.z; Ws[c4 + 3][r] = vw.w;
        }
        __syncthreads();

#pragma unroll
        for (int kk = 0; kk < BK; kk++) {
            float a[4], b[4];
#pragma unroll
            for (int i = 0; i < 4; i++) a[i] = Xs[kk][ty * 4 + i];
#pragma unroll
            for (int j = 0; j < 4; j++) b[j] = Ws[kk][tx * 4 + j];
#pragma unroll
            for (int i = 0; i < 4; i++)
#pragma unroll
                for (int j = 0; j < 4; j++) acc[i][j] = fmaf(a[i], b[j], acc[i][j]);
        }
        __syncthreads();
    }

#pragma unroll
    for (int i = 0; i < 4; i++) {
        const int m = m0 + ty * 4 + i;
#pragma unroll
        for (int j = 0; j < 4; j++) {
            const int n = n0 + tx * 4 + j;
            const float v = acc[i][j] + bias[n];
            if (MODE == 0) {
                Y[(size_t)m * N + n] = v;
            } else {
                const int b_ = m / SEQ, t_ = m % SEQ;
                const int h_ = n / DK,  d_ = n % DK;
                Y[((((size_t)b_ * HEADS + h_) * SEQ) + t_) * DK + d_] = v;
            }
        }
    }
}

// ---------------------------------------------------------------------------
// Flash-attention-style fused attention.
// One block per (b, h, 64-query tile). 256 threads (16x16).
// Each thread owns 4 query rows (ty*4+ri). S tile cols: tx*2 (BKV=32);
// O accumulator dims: tx*4 (DK=64). Online softmax with shuffle row-reduce.
// Writes ctx in [B,T,DM] layout (feature = h*64+d) for the output GEMM.
// ---------------------------------------------------------------------------
__global__ void attention_kernel(float* __restrict__ ctx)
{
    const int BQ = 64, BKV = 32;
    __shared__ float Qs[BQ][DK + 1];
    __shared__ float Ks[BKV][DK + 1];
    __shared__ float Vs[BKV][DK + 1];
    __shared__ float Ps[BQ][BKV + 1];

    const int tid = threadIdx.x;
    const int tx = tid & 15;
    const int ty = tid >> 4;
    const int qb = blockIdx.x;   // 0..31
    const int h  = blockIdx.y;
    const int b  = blockIdx.z;

    const float* Qb = g_Q + (((size_t)b * HEADS + h) * SEQ + qb * BQ) * DK;
    const float* Kb = g_K + (((size_t)b * HEADS + h) * SEQ) * DK;
    const float* Vb = g_V + (((size_t)b * HEADS + h) * SEQ) * DK;

    // Load Q tile: 64x64 floats = 1024 float4, 4 per thread
    for (int i = tid; i < BQ * DK / 4; i += 256) {
        const int row = i >> 4;
        const int c4  = (i & 15) << 2;
        float4 v = *reinterpret_cast<const float4*>(&Qb[row * DK + c4]);
        Qs[row][c4 + 0] = v.x; Qs[row][c4 + 1] = v.y;
        Qs[row][c4 + 2] = v.z; Qs[row][c4 + 3] = v.w;
    }

    float m_i[4], l_i[4], acc[4][4];
#pragma unroll
    for (int i = 0; i < 4; i++) {
        m_i[i] = -INFINITY; l_i[i] = 0.f;
#pragma unroll
        for (int j = 0; j < 4; j++) acc[i][j] = 0.f;
    }

    const float scale = 0.125f;  // 1/sqrt(64)

    for (int kb = 0; kb < SEQ; kb += BKV) {
        __syncthreads();  // prior iter done reading Ks/Vs (also covers Qs load on iter 0)

        // Load K,V tiles: 32x64 floats = 512 float4 each, 2 per thread each
        for (int i = tid; i < BKV * DK / 4; i += 256) {
            const int row = i >> 4;
            const int c4  = (i & 15) << 2;
            float4 kv = *reinterpret_cast<const float4*>(&Kb[(size_t)(kb + row) * DK + c4]);
            Ks[row][c4 + 0] = kv.x; Ks[row][c4 + 1] = kv.y;
            Ks[row][c4 + 2] = kv.z; Ks[row][c4 + 3] = kv.w;
            float4 vv = *reinterpret_cast<const float4*>(&Vb[(size_t)(kb + row) * DK + c4]);
            Vs[row][c4 + 0] = vv.x; Vs[row][c4 + 1] = vv.y;
            Vs[row][c4 + 2] = vv.z; Vs[row][c4 + 3] = vv.w;
        }
        __syncthreads();

        // S = scale * Q K^T : each thread 4 rows x 2 cols
        float s[4][2];
#pragma unroll
        for (int i = 0; i < 4; i++)
#pragma unroll
            for (int j = 0; j < 2; j++) s[i][j] = 0.f;

        for (int d = 0; d < DK; d++) {
            float a[4], kcol[2];
#pragma unroll
            for (int i = 0; i < 4; i++) a[i] = Qs[ty * 4 + i][d];
#pragma unroll
            for (int j = 0; j < 2; j++) kcol[j] = Ks[tx * 2 + j][d];
#pragma unroll
            for (int i = 0; i < 4; i++)
#pragma unroll
                for (int j = 0; j < 2; j++) s[i][j] = fmaf(a[i], kcol[j], s[i][j]);
        }
#pragma unroll
        for (int i = 0; i < 4; i++)
#pragma unroll
            for (int j = 0; j < 2; j++) s[i][j] *= scale;

        // Online softmax per query row (reduce over 16 tx lanes via shuffle;
        // lane = (ty&1)*16 + tx, xor on bits 0..3 stays in the same ty group)
#pragma unroll
        for (int i = 0; i < 4; i++) {
            float mloc = fmaxf(s[i][0], s[i][1]);
#pragma unroll
            for (int off = 8; off >= 1; off >>= 1)
                mloc = fmaxf(mloc, __shfl_xor_sync(0xffffffffu, mloc, off));
            const float m_new = fmaxf(m_i[i], mloc);
            const float alpha = __expf(m_i[i] - m_new);  // 0 on first iter (-inf)
            float p0 = __expf(s[i][0] - m_new);
            float p1 = __expf(s[i][1] - m_new);
            float rsum = p0 + p1;
#pragma unroll
            for (int off = 8; off >= 1; off >>= 1)
                rsum += __shfl_xor_sync(0xffffffffu, rsum, off);
            l_i[i] = l_i[i] * alpha + rsum;
            m_i[i] = m_new;
#pragma unroll
            for (int j = 0; j < 4; j++) acc[i][j] *= alpha;
            Ps[ty * 4 + i][tx * 2 + 0] = p0;
            Ps[ty * 4 + i][tx * 2 + 1] = p1;
        }
        __syncthreads();

        // O += P @ V : each thread 4 rows x 4 dims
        for (int j = 0; j < BKV; j++) {
            float p[4], v[4];
#pragma unroll
            for (int i = 0; i < 4; i++) p[i] = Ps[ty * 4 + i][j];
#pragma unroll
            for (int c = 0; c < 4; c++) v[c] = Vs[j][tx * 4 + c];
#pragma unroll
            for (int i = 0; i < 4; i++)
#pragma unroll
                for (int c = 0; c < 4; c++) acc[i][c] = fmaf(p[i], v[c], acc[i][c]);
        }
    }

    // Write ctx[b, t, h*64 + d] = acc / l
#pragma unroll
    for (int i = 0; i < 4; i++) {
        const int t = qb * BQ + ty * 4 + i;
        const float inv_l = 1.f / l_i[i];
#pragma unroll
        for (int c = 0; c < 4; c++) {
            const int d = tx * 4 + c;
            ctx[(((size_t)b * SEQ) + t) * DM + h * DK + d] = acc[i][c] * inv_l;
        }
    }
}

// ---------------------------------------------------------------------------
// Launch
// Inputs (metadata order): x, W_q, b_q, W_k, b_k, W_v, b_v, W_out, b_out
// ---------------------------------------------------------------------------
extern "C" void kernel_launch(void* const* d_in, const int* in_sizes, int n_in,
                              void* d_out, int out_size)
{
    const float* x    = (const float*)d_in[0];
    const float* W_q  = (const float*)d_in[1];
    const float* b_q  = (const float*)d_in[2];
    const float* W_k  = (const float*)d_in[3];
    const float* b_k  = (const float*)d_in[4];
    const float* W_v  = (const float*)d_in[5];
    const float* b_v  = (const float*)d_in[6];
    const float* W_o  = (const float*)d_in[7];
    const float* b_o  = (const float*)d_in[8];

    float *Qd, *Kd, *Vd, *ctxd;
    cudaGetSymbolAddress((void**)&Qd,   g_Q);
    cudaGetSymbolAddress((void**)&Kd,   g_K);
    cudaGetSymbolAddress((void**)&Vd,   g_V);
    cudaGetSymbolAddress((void**)&ctxd, g_ctx);

    const dim3 gemm_grid(DM / 64, MROWS / 64);  // (16, 64)
    const dim3 gemm_blk(256);

    gemm_bias_kernel<1><<<gemm_grid, gemm_blk>>>(x, W_q, b_q, Qd, MROWS, DM, DM);
    gemm_bias_kernel<1><<<gemm_grid, gemm_blk>>>(x, W_k, b_k, Kd, MROWS, DM, DM);
    gemm_bias_kernel<1><<<gemm_grid, gemm_blk>>>(x, W_v, b_v, Vd, MROWS, DM, DM);

    const dim3 attn_grid(SEQ / 64, HEADS, BATCH);  // (32, 16, 2)
    attention_kernel<<<attn_grid, gemm_blk>>>(ctxd);

    gemm_bias_kernel<0><<<gemm_grid, gemm_blk>>>(ctxd, W_o, b_o, (float*)d_out,
                                                 MROWS, DM, DM);
}

// round 2
// speedup vs baseline: 3.6859x; 3.6859x over previous
#include <cuda_runtime.h>
#include <math.h>
#include <stdint.h>

// Problem constants
#define BATCH 2
#define SEQ   2048
#define HEADS 16
#define DK    64
#define DM    1024
#define MROWS (BATCH * SEQ)   // 4096

// Scratch (device globals — no allocation allowed)
__device__ float g_Q[BATCH * HEADS * SEQ * DK];   // [B,H,T,dk]
__device__ float g_K[BATCH * HEADS * SEQ * DK];
__device__ float g_V[BATCH * HEADS * SEQ * DK];
__device__ float g_ctx[BATCH * SEQ * DM];         // [B,T,DM]

__device__ __forceinline__ float to_tf32(float x) {
    float y;
    asm("cvt.rna.tf32.f32 %0, %1;" : "=f"(y) : "f"(x));
    return y;
}
__device__ __forceinline__ uint32_t f2u(float x) { return __float_as_uint(x); }

// D += A(16x8 tf32 row) * B(8x8 tf32 col)
__device__ __forceinline__ void mma_m16n8k8(float c[4],
    uint32_t a0, uint32_t a1, uint32_t a2, uint32_t a3,
    uint32_t b0, uint32_t b1)
{
    asm volatile(
        "mma.sync.aligned.m16n8k8.row.col.f32.tf32.tf32.f32 "
        "{%0,%1,%2,%3}, {%4,%5,%6,%7}, {%8,%9}, {%0,%1,%2,%3};\n"
        : "+f"(c[0]), "+f"(c[1]), "+f"(c[2]), "+f"(c[3])
        : "r"(a0), "r"(a1), "r"(a2), "r"(a3), "r"(b0), "r"(b1));
}

// ---------------------------------------------------------------------------
// tf32 tensor-core GEMM: Y = X @ W^T + bias.
// X:[M,K] row-major, W:[N,K] row-major.
// Block tile 128x128, BK=32. 8 warps in 4(M) x 2(N); warp tile 32x64.
// MODE 0: Y[m*N+n]. MODE 1: scatter to [B,H,T,dk].
// smem stride 36 (== 4 mod 32) => conflict-free fragment LDS.
// ---------------------------------------------------------------------------
#define GTS 36

template <int MODE>
__global__ __launch_bounds__(256)
void gemm_tf32_kernel(const float* __restrict__ X,
                      const float* __restrict__ W,
                      const float* __restrict__ bias,
                      float* __restrict__ Y,
                      int M, int N, int K)
{
    __shared__ float Xs[128][GTS];
    __shared__ float Ws[128][GTS];

    const int tid  = threadIdx.x;
    const int warp = tid >> 5, lane = tid & 31;
    const int g = lane >> 2, t = lane & 3;
    const int wm = warp >> 1;     // 0..3  (M dir, 32 rows each)
    const int wn = warp & 1;      // 0..1  (N dir, 64 cols each)
    const int m0 = blockIdx.y * 128;
    const int n0 = blockIdx.x * 128;

    float acc[2][8][4];
#pragma unroll
    for (int mf = 0; mf < 2; mf++)
#pragma unroll
        for (int nf = 0; nf < 8; nf++)
#pragma unroll
            for (int j = 0; j < 4; j++) acc[mf][nf][j] = 0.f;

    for (int k0 = 0; k0 < K; k0 += 32) {
        __syncthreads();
        // Load 128x32 tiles of X and W (float4, cvt to tf32 on store)
#pragma unroll
        for (int i = 0; i < 4; i++) {
            const int idx = tid + i * 256;         // 0..1023
            const int row = idx >> 3;              // 0..127
            const int c4  = (idx & 7) << 2;        // 0,4,...,28
            float4 vx = *reinterpret_cast<const float4*>(&X[(size_t)(m0 + row) * K + k0 + c4]);
            vx.x = to_tf32(vx.x); vx.y = to_tf32(vx.y);
            vx.z = to_tf32(vx.z); vx.w = to_tf32(vx.w);
            *reinterpret_cast<float4*>(&Xs[row][c4]) = vx;
            float4 vw = *reinterpret_cast<const float4*>(&W[(size_t)(n0 + row) * K + k0 + c4]);
            vw.x = to_tf32(vw.x); vw.y = to_tf32(vw.y);
            vw.z = to_tf32(vw.z); vw.w = to_tf32(vw.w);
            *reinterpret_cast<float4*>(&Ws[row][c4]) = vw;
        }
        __syncthreads();

#pragma unroll
        for (int kk = 0; kk < 4; kk++) {
            uint32_t a[2][4];
#pragma unroll
            for (int mf = 0; mf < 2; mf++) {
                const int r = wm * 32 + mf * 16;
                a[mf][0] = f2u(Xs[r + g    ][kk * 8 + t    ]);
                a[mf][1] = f2u(Xs[r + g + 8][kk * 8 + t    ]);
                a[mf][2] = f2u(Xs[r + g    ][kk * 8 + t + 4]);
                a[mf][3] = f2u(Xs[r + g + 8][kk * 8 + t + 4]);
            }
#pragma unroll
            for (int nf = 0; nf < 8; nf++) {
                const uint32_t b0 = f2u(Ws[wn * 64 + nf * 8 + g][kk * 8 + t    ]);
                const uint32_t b1 = f2u(Ws[wn * 64 + nf * 8 + g][kk * 8 + t + 4]);
#pragma unroll
                for (int mf = 0; mf < 2; mf++)
                    mma_m16n8k8(acc[mf][nf], a[mf][0], a[mf][1], a[mf][2], a[mf][3], b0, b1);
            }
        }
    }

    // Epilogue
#pragma unroll
    for (int mf = 0; mf < 2; mf++) {
        const int m = m0 + wm * 32 + mf * 16 + g;
#pragma unroll
        for (int nf = 0; nf < 8; nf++) {
            const int n = n0 + wn * 64 + nf * 8 + 2 * t;
            const float bn0 = bias[n], bn1 = bias[n + 1];
            float2 lo = make_float2(acc[mf][nf][0] + bn0, acc[mf][nf][1] + bn1);
            float2 hi = make_float2(acc[mf][nf][2] + bn0, acc[mf][nf][3] + bn1);
            if (MODE == 0) {
                *reinterpret_cast<float2*>(&Y[(size_t)m * N + n]) = lo;
                *reinterpret_cast<float2*>(&Y[(size_t)(m + 8) * N + n]) = hi;
            } else {
                const int h_ = n / DK, d_ = n % DK;
                const int b0_ = m / SEQ, t0_ = m % SEQ;
                const int b1_ = (m + 8) / SEQ, t1_ = (m + 8) % SEQ;
                *reinterpret_cast<float2*>(
                    &Y[((((size_t)b0_ * HEADS + h_) * SEQ) + t0_) * DK + d_]) = lo;
                *reinterpret_cast<float2*>(
                    &Y[((((size_t)b1_ * HEADS + h_) * SEQ) + t1_) * DK + d_]) = hi;
            }
        }
    }
}

// ---------------------------------------------------------------------------
// Flash attention with tf32 mma.
// Block = (b, h, 128-query tile). 256 threads = 8 warps; each warp owns 16
// query rows (full softmax rows stay inside one warp). KV tiles of 64.
// smem strides: 68 (==4 mod 32) for row-major A/B-as-K tiles, 72 (==8 mod 32)
// for V tile (B operand indexed k-major) — both conflict-free.
// ---------------------------------------------------------------------------
#define QS_STRIDE 68
#define KS_STRIDE 68
#define VS_STRIDE 72
#define PS_STRIDE 68
#define ATTN_SMEM_FLOATS (128*QS_STRIDE + 64*KS_STRIDE + 64*VS_STRIDE + 128*PS_STRIDE)

__global__ __launch_bounds__(256)
void attn_tf32_kernel(const float* __restrict__ Q,
                      const float* __restrict__ K,
                      const float* __restrict__ V,
                      float* __restrict__ ctx)
{
    extern __shared__ float smf[];
    float* Qs = smf;                          // [128][68]
    float* Ks = Qs + 128 * QS_STRIDE;         // [64][68]
    float* Vs = Ks + 64 * KS_STRIDE;          // [64][72]
    float* Ps = Vs + 64 * VS_STRIDE;          // [128][68]

    const int tid  = threadIdx.x;
    const int warp = tid >> 5, lane = tid & 31;
    const int g = lane >> 2, t = lane & 3;
    const int qb = blockIdx.x;  // 0..15
    const int h  = blockIdx.y;
    const int b  = blockIdx.z;

    const size_t head_off = ((size_t)b * HEADS + h) * SEQ * DK;
    const float* Qg = Q + head_off + (size_t)qb * 128 * DK;
    const float* Kg = K + head_off;
    const float* Vg = V + head_off;

    // fold 1/sqrt(dk) and log2(e) into Q; softmax done with exp2
    const float qscale = 0.125f * 1.4426950408889634f;

    // Load Q tile 128x64 (2048 float4, 8 per thread)
#pragma unroll
    for (int i = 0; i < 8; i++) {
        const int idx = tid + i * 256;
        const int row = idx >> 4;
        const int c4  = (idx & 15) << 2;
        float4 v = *reinterpret_cast<const float4*>(&Qg[(size_t)row * DK + c4]);
        v.x = to_tf32(v.x * qscale); v.y = to_tf32(v.y * qscale);
        v.z = to_tf32(v.z * qscale); v.w = to_tf32(v.w * qscale);
        *reinterpret_cast<float4*>(&Qs[row * QS_STRIDE + c4]) = v;
    }

    float O[8][4];
#pragma unroll
    for (int nf = 0; nf < 8; nf++)
#pragma unroll
        for (int j = 0; j < 4; j++) O[nf][j] = 0.f;
    float mrow0 = -INFINITY, mrow1 = -INFINITY;
    float lrow0 = 0.f, lrow1 = 0.f;

    const int qrow = warp * 16;

    for (int kb = 0; kb < SEQ; kb += 64) {
        __syncthreads();   // all warps done reading prev Ks/Vs (covers Qs fill on iter 0)
        // Load K,V tiles 64x64 each (1024 float4 each, 4 per thread each)
#pragma unroll
        for (int i = 0; i < 4; i++) {
            const int idx = tid + i * 256;
            const int row = idx >> 4;
            const int c4  = (idx & 15) << 2;
            float4 kv = *reinterpret_cast<const float4*>(&Kg[(size_t)(kb + row) * DK + c4]);
            kv.x = to_tf32(kv.x); kv.y = to_tf32(kv.y);
            kv.z = to_tf32(kv.z); kv.w = to_tf32(kv.w);
            *reinterpret_cast<float4*>(&Ks[row * KS_STRIDE + c4]) = kv;
            float4 vv = *reinterpret_cast<const float4*>(&Vg[(size_t)(kb + row) * DK + c4]);
            vv.x = to_tf32(vv.x); vv.y = to_tf32(vv.y);
            vv.z = to_tf32(vv.z); vv.w = to_tf32(vv.w);
            *reinterpret_cast<float4*>(&Vs[row * VS_STRIDE + c4]) = vv;
        }
        __syncthreads();

        // S = Qtile(16 rows) @ K^T  -> s[8][4] per lane
        float s[8][4];
#pragma unroll
        for (int nf = 0; nf < 8; nf++)
#pragma unroll
            for (int j = 0; j < 4; j++) s[nf][j] = 0.f;

#pragma unroll
        for (int kk = 0; kk < 8; kk++) {
            const uint32_t a0 = f2u(Qs[(qrow + g    ) * QS_STRIDE + kk * 8 + t    ]);
            const uint32_t a1 = f2u(Qs[(qrow + g + 8) * QS_STRIDE + kk * 8 + t    ]);
            const uint32_t a2 = f2u(Qs[(qrow + g    ) * QS_STRIDE + kk * 8 + t + 4]);
            const uint32_t a3 = f2u(Qs[(qrow + g + 8) * QS_STRIDE + kk * 8 + t + 4]);
#pragma unroll
            for (int nf = 0; nf < 8; nf++) {
                const uint32_t b0 = f2u(Ks[(nf * 8 + g) * KS_STRIDE + kk * 8 + t    ]);
                const uint32_t b1 = f2u(Ks[(nf * 8 + g) * KS_STRIDE + kk * 8 + t + 4]);
                mma_m16n8k8(s[nf], a0, a1, a2, a3, b0, b1);
            }
        }

        // Online softmax (rows qrow+g and qrow+g+8 owned by the lane-quad)
        float ml0 = -INFINITY, ml1 = -INFINITY;
#pragma unroll
        for (int nf = 0; nf < 8; nf++) {
            ml0 = fmaxf(ml0, fmaxf(s[nf][0], s[nf][1]));
            ml1 = fmaxf(ml1, fmaxf(s[nf][2], s[nf][3]));
        }
        ml0 = fmaxf(ml0, __shfl_xor_sync(0xffffffffu, ml0, 1));
        ml0 = fmaxf(ml0, __shfl_xor_sync(0xffffffffu, ml0, 2));
        ml1 = fmaxf(ml1, __shfl_xor_sync(0xffffffffu, ml1, 1));
        ml1 = fmaxf(ml1, __shfl_xor_sync(0xffffffffu, ml1, 2));
        const float mn0 = fmaxf(mrow0, ml0);
        const float mn1 = fmaxf(mrow1, ml1);
        const float alpha0 = exp2f(mrow0 - mn0);
        const float alpha1 = exp2f(mrow1 - mn1);

        float rs0 = 0.f, rs1 = 0.f;
#pragma unroll
        for (int nf = 0; nf < 8; nf++) {
            s[nf][0] = exp2f(s[nf][0] - mn0);
            s[nf][1] = exp2f(s[nf][1] - mn0);
            s[nf][2] = exp2f(s[nf][2] - mn1);
            s[nf][3] = exp2f(s[nf][3] - mn1);
            rs0 += s[nf][0] + s[nf][1];
            rs1 += s[nf][2] + s[nf][3];
        }
        rs0 += __shfl_xor_sync(0xffffffffu, rs0, 1);
        rs0 += __shfl_xor_sync(0xffffffffu, rs0, 2);
        rs1 += __shfl_xor_sync(0xffffffffu, rs1, 1);
        rs1 += __shfl_xor_sync(0xffffffffu, rs1, 2);
        lrow0 = lrow0 * alpha0 + rs0;
        lrow1 = lrow1 * alpha1 + rs1;
        mrow0 = mn0; mrow1 = mn1;

#pragma unroll
        for (int nf = 0; nf < 8; nf++) {
            O[nf][0] *= alpha0; O[nf][1] *= alpha0;
            O[nf][2] *= alpha1; O[nf][3] *= alpha1;
        }

        // Store P (tf32) into this warp's private Ps rows
#pragma unroll
        for (int nf = 0; nf < 8; nf++) {
            float2 p01 = make_float2(to_tf32(s[nf][0]), to_tf32(s[nf][1]));
            float2 p23 = make_float2(to_tf32(s[nf][2]), to_tf32(s[nf][3]));
            *reinterpret_cast<float2*>(&Ps[(qrow + g    ) * PS_STRIDE + nf * 8 + 2 * t]) = p01;
            *reinterpret_cast<float2*>(&Ps[(qrow + g + 8) * PS_STRIDE + nf * 8 + 2 * t]) = p23;
        }
        __syncwarp();

        // O += P @ V   (A = Ps 16x64 over kv; B = Vs (kv, dk))
#pragma unroll
        for (int kk = 0; kk < 8; kk++) {
            const uint32_t a0 = f2u(Ps[(qrow + g    ) * PS_STRIDE + kk * 8 + t    ]);
            const uint32_t a1 = f2u(Ps[(qrow + g + 8) * PS_STRIDE + kk * 8 + t    ]);
            const uint32_t a2 = f2u(Ps[(qrow + g    ) * PS_STRIDE + kk * 8 + t + 4]);
            const uint32_t a3 = f2u(Ps[(qrow + g + 8) * PS_STRIDE + kk * 8 + t + 4]);
#pragma unroll
            for (int nf = 0; nf < 8; nf++) {
                const uint32_t b0 = f2u(Vs[(kk * 8 + t    ) * VS_STRIDE + nf * 8 + g]);
                const uint32_t b1 = f2u(Vs[(kk * 8 + t + 4) * VS_STRIDE + nf * 8 + g]);
                mma_m16n8k8(O[nf], a0, a1, a2, a3, b0, b1);
            }
        }
    }

    // Epilogue: normalize, write ctx[b][t][h*64+d]
    const float inv0 = 1.f / lrow0;
    const float inv1 = 1.f / lrow1;
    const int t0 = qb * 128 + qrow + g;
#pragma unroll
    for (int nf = 0; nf < 8; nf++) {
        const int d = h * DK + nf * 8 + 2 * t;
        float2 lo = make_float2(O[nf][0] * inv0, O[nf][1] * inv0);
        float2 hi = make_float2(O[nf][2] * inv1, O[nf][3] * inv1);
        *reinterpret_cast<float2*>(&ctx[((size_t)b * SEQ + t0    ) * DM + d]) = lo;
        *reinterpret_cast<float2*>(&ctx[((size_t)b * SEQ + t0 + 8) * DM + d]) = hi;
    }
}

// ---------------------------------------------------------------------------
// Launch. Inputs: x, W_q, b_q, W_k, b_k, W_v, b_v, W_out, b_out
// ---------------------------------------------------------------------------
extern "C" void kernel_launch(void* const* d_in, const int* in_sizes, int n_in,
                              void* d_out, int out_size)
{
    const float* x   = (const float*)d_in[0];
    const float* W_q = (const float*)d_in[1];
    const float* b_q = (const float*)d_in[2];
    const float* W_k = (const float*)d_in[3];
    const float* b_k = (const float*)d_in[4];
    const float* W_v = (const float*)d_in[5];
    const float* b_v = (const float*)d_in[6];
    const float* W_o = (const float*)d_in[7];
    const float* b_o = (const float*)d_in[8];

    float *Qd, *Kd, *Vd, *ctxd;
    cudaGetSymbolAddress((void**)&Qd,   g_Q);
    cudaGetSymbolAddress((void**)&Kd,   g_K);
    cudaGetSymbolAddress((void**)&Vd,   g_V);
    cudaGetSymbolAddress((void**)&ctxd, g_ctx);

    const size_t attn_smem = ATTN_SMEM_FLOATS * sizeof(float);  // 105,472 B
    cudaFuncSetAttribute(attn_tf32_kernel,
                         cudaFuncAttributeMaxDynamicSharedMemorySize,
                         (int)attn_smem);

    const dim3 gemm_grid(DM / 128, MROWS / 128);  // (8, 32)
    const dim3 blk(256);

    gemm_tf32_kernel<1><<<gemm_grid, blk>>>(x, W_q, b_q, Qd, MROWS, DM, DM);
    gemm_tf32_kernel<1><<<gemm_grid, blk>>>(x, W_k, b_k, Kd, MROWS, DM, DM);
    gemm_tf32_kernel<1><<<gemm_grid, blk>>>(x, W_v, b_v, Vd, MROWS, DM, DM);

    const dim3 attn_grid(SEQ / 128, HEADS, BATCH);  // (16, 16, 2)
    attn_tf32_kernel<<<attn_grid, blk, attn_smem>>>(Qd, Kd, Vd, ctxd);

    gemm_tf32_kernel<0><<<gemm_grid, blk>>>(ctxd, W_o, b_o, (float*)d_out,
                                            MROWS, DM, DM);
}

// round 3
// speedup vs baseline: 3.9237x; 1.0645x over previous
#include <cuda_runtime.h>
#include <math.h>
#include <stdint.h>

// Problem constants
#define BATCH 2
#define SEQ   2048
#define HEADS 16
#define DK    64
#define DM    1024
#define MROWS (BATCH * SEQ)   // 4096

// Scratch (device globals — no allocation allowed)
__device__ float g_X[MROWS * DM];          // tf32-rounded x
__device__ float g_Wall[4 * DM * DM];      // tf32-rounded Wq,Wk,Wv,Wo
__device__ float g_Q[BATCH * HEADS * SEQ * DK];
__device__ float g_K[BATCH * HEADS * SEQ * DK];
__device__ float g_V[BATCH * HEADS * SEQ * DK];
__device__ float g_ctx[MROWS * DM];

__device__ __forceinline__ float to_tf32(float x) {
    float y;
    asm("cvt.rna.tf32.f32 %0, %1;" : "=f"(y) : "f"(x));
    return y;
}
__device__ __forceinline__ uint32_t f2u(float x) { return __float_as_uint(x); }

__device__ __forceinline__ float ex2f_(float x) {
    float y;
    asm("ex2.approx.ftz.f32 %0, %1;" : "=f"(y) : "f"(x));
    return y;
}

__device__ __forceinline__ void mma_m16n8k8(float c[4],
    uint32_t a0, uint32_t a1, uint32_t a2, uint32_t a3,
    uint32_t b0, uint32_t b1)
{
    asm volatile(
        "mma.sync.aligned.m16n8k8.row.col.f32.tf32.tf32.f32 "
        "{%0,%1,%2,%3}, {%4,%5,%6,%7}, {%8,%9}, {%0,%1,%2,%3};\n"
        : "+f"(c[0]), "+f"(c[1]), "+f"(c[2]), "+f"(c[3])
        : "r"(a0), "r"(a1), "r"(a2), "r"(a3), "r"(b0), "r"(b1));
}

__device__ __forceinline__ void cp16(float* smem_dst, const float* gsrc) {
    uint32_t s = (uint32_t)__cvta_generic_to_shared(smem_dst);
    asm volatile("cp.async.cg.shared.global [%0], [%1], 16;\n" :: "r"(s), "l"(gsrc));
}
__device__ __forceinline__ void cp_commit() {
    asm volatile("cp.async.commit_group;\n");
}
template <int N>
__device__ __forceinline__ void cp_wait() {
    asm volatile("cp.async.wait_group %0;\n" :: "n"(N));
}

// ---------------------------------------------------------------------------
// Prepass: round x and the 4 weight matrices to tf32 (rna) once.
// After this every downstream load may truncate freely (identity on tf32).
// ---------------------------------------------------------------------------
__global__ void prepass_kernel(const float4* __restrict__ x,
                               const float4* __restrict__ wq,
                               const float4* __restrict__ wk,
                               const float4* __restrict__ wv,
                               const float4* __restrict__ wo)
{
    const int i = blockIdx.x * blockDim.x + threadIdx.x;
    float4* X4 = reinterpret_cast<float4*>(g_X);
    float4* W4 = reinterpret_cast<float4*>(g_Wall);
    if (i < MROWS * DM / 4) {
        float4 v = x[i];
        v.x = to_tf32(v.x); v.y = to_tf32(v.y); v.z = to_tf32(v.z); v.w = to_tf32(v.w);
        X4[i] = v;
    }
    if (i < DM * DM / 4) {
        const int WQ = DM * DM / 4;
        float4 v;
        v = wq[i];
        v.x = to_tf32(v.x); v.y = to_tf32(v.y); v.z = to_tf32(v.z); v.w = to_tf32(v.w);
        W4[i] = v;
        v = wk[i];
        v.x = to_tf32(v.x); v.y = to_tf32(v.y); v.z = to_tf32(v.z); v.w = to_tf32(v.w);
        W4[i + WQ] = v;
        v = wv[i];
        v.x = to_tf32(v.x); v.y = to_tf32(v.y); v.z = to_tf32(v.z); v.w = to_tf32(v.w);
        W4[i + 2 * WQ] = v;
        v = wo[i];
        v.x = to_tf32(v.x); v.y = to_tf32(v.y); v.z = to_tf32(v.z); v.w = to_tf32(v.w);
        W4[i + 3 * WQ] = v;
    }
}

// ---------------------------------------------------------------------------
// tf32 GEMM body: Y = X @ W^T + bias.  X:[M,K]=[4096,1024], W:[N,K]=[1024,1024].
// 128x128 block tile, BK=32, cp.async double-buffered, ONE syncthreads/k-step.
// MODE 0: plain [M,N] store (fp32). MODE 1: scatter to [B,H,T,dk], tf32-rounded.
// smem stride 36 (==4 mod 32): conflict-free fragment LDS.
// ---------------------------------------------------------------------------
#define GTS 36

template <int MODE>
__device__ __forceinline__ void gemm_body(const float* __restrict__ X,
                                          const float* __restrict__ W,
                                          const float* __restrict__ bias,
                                          float* __restrict__ Y)
{
    extern __shared__ float sm[];
    float* Xs = sm;                      // [2][128*36]
    float* Ws = sm + 2 * 128 * GTS;      // [2][128*36]

    const int tid  = threadIdx.x;
    const int warp = tid >> 5, lane = tid & 31;
    const int g = lane >> 2, t = lane & 3;
    const int wm = warp >> 1;            // 0..3
    const int wn = warp & 1;             // 0..1
    const int m0 = blockIdx.y * 128;
    const int n0 = blockIdx.x * 128;

    float acc[2][8][4];
#pragma unroll
    for (int mf = 0; mf < 2; mf++)
#pragma unroll
        for (int nf = 0; nf < 8; nf++)
#pragma unroll
            for (int j = 0; j < 4; j++) acc[mf][nf][j] = 0.f;

    const int NKB = DM / 32;  // 32

    // prologue: stage tile 0
#pragma unroll
    for (int i = 0; i < 4; i++) {
        const int idx = tid + i * 256;
        const int row = idx >> 3, c4 = (idx & 7) << 2;
        cp16(&Xs[row * GTS + c4], &X[(size_t)(m0 + row) * DM + c4]);
        cp16(&Ws[row * GTS + c4], &W[(size_t)(n0 + row) * DM + c4]);
    }
    cp_commit();

    for (int kb = 0; kb < NKB; kb++) {
        const int cur = kb & 1;
        cp_wait<0>();
        __syncthreads();   // tile kb visible to all; prior compute(kb-1) done

        if (kb + 1 < NKB) {
            const int k0 = (kb + 1) * 32;
            const int nb = (kb + 1) & 1;
#pragma unroll
            for (int i = 0; i < 4; i++) {
                const int idx = tid + i * 256;
                const int row = idx >> 3, c4 = (idx & 7) << 2;
                cp16(&Xs[nb * 128 * GTS + row * GTS + c4],
                     &X[(size_t)(m0 + row) * DM + k0 + c4]);
                cp16(&Ws[nb * 128 * GTS + row * GTS + c4],
                     &W[(size_t)(n0 + row) * DM + k0 + c4]);
            }
            cp_commit();
        }

        const float* Xc = Xs + cur * 128 * GTS;
        const float* Wc = Ws + cur * 128 * GTS;
#pragma unroll
        for (int kk = 0; kk < 4; kk++) {
            uint32_t a[2][4];
#pragma unroll
            for (int mf = 0; mf < 2; mf++) {
                const int r = wm * 32 + mf * 16;
                a[mf][0] = f2u(Xc[(r + g    ) * GTS + kk * 8 + t    ]);
                a[mf][1] = f2u(Xc[(r + g + 8) * GTS + kk * 8 + t    ]);
                a[mf][2] = f2u(Xc[(r + g    ) * GTS + kk * 8 + t + 4]);
                a[mf][3] = f2u(Xc[(r + g + 8) * GTS + kk * 8 + t + 4]);
            }
#pragma unroll
            for (int nf = 0; nf < 8; nf++) {
                const uint32_t b0 = f2u(Wc[(wn * 64 + nf * 8 + g) * GTS + kk * 8 + t    ]);
                const uint32_t b1 = f2u(Wc[(wn * 64 + nf * 8 + g) * GTS + kk * 8 + t + 4]);
#pragma unroll
                for (int mf = 0; mf < 2; mf++)
                    mma_m16n8k8(acc[mf][nf], a[mf][0], a[mf][1], a[mf][2], a[mf][3], b0, b1);
            }
        }
    }

    // Epilogue
#pragma unroll
    for (int mf = 0; mf < 2; mf++) {
        const int m = m0 + wm * 32 + mf * 16 + g;
#pragma unroll
        for (int nf = 0; nf < 8; nf++) {
            const int n = n0 + wn * 64 + nf * 8 + 2 * t;
            const float bn0 = bias[n], bn1 = bias[n + 1];
            if (MODE == 0) {
                float2 lo = make_float2(acc[mf][nf][0] + bn0, acc[mf][nf][1] + bn1);
                float2 hi = make_float2(acc[mf][nf][2] + bn0, acc[mf][nf][3] + bn1);
                *reinterpret_cast<float2*>(&Y[(size_t)m * DM + n]) = lo;
                *reinterpret_cast<float2*>(&Y[(size_t)(m + 8) * DM + n]) = hi;
            } else {
                // round to tf32 so attention can load raw
                float2 lo = make_float2(to_tf32(acc[mf][nf][0] + bn0),
                                        to_tf32(acc[mf][nf][1] + bn1));
                float2 hi = make_float2(to_tf32(acc[mf][nf][2] + bn0),
                                        to_tf32(acc[mf][nf][3] + bn1));
                const int h_ = n / DK, d_ = n % DK;
                const int b0_ = m / SEQ, t0_ = m % SEQ;
                const int b1_ = (m + 8) / SEQ, t1_ = (m + 8) % SEQ;
                *reinterpret_cast<float2*>(
                    &Y[((((size_t)b0_ * HEADS + h_) * SEQ) + t0_) * DK + d_]) = lo;
                *reinterpret_cast<float2*>(
                    &Y[((((size_t)b1_ * HEADS + h_) * SEQ) + t1_) * DK + d_]) = hi;
            }
        }
    }
}

// Fused QKV projection: blockIdx.z selects {q,k,v}
__global__ __launch_bounds__(256, 2)
void gemm_qkv_kernel(const float* __restrict__ bq,
                     const float* __restrict__ bk,
                     const float* __restrict__ bv)
{
    const int z = blockIdx.z;
    const float* W    = g_Wall + (size_t)z * DM * DM;
    const float* bias = (z == 0) ? bq : (z == 1) ? bk : bv;
    float* Y          = (z == 0) ? g_Q : (z == 1) ? g_K : g_V;
    gemm_body<1>(g_X, W, bias, Y);
}

__global__ __launch_bounds__(256, 2)
void gemm_out_kernel(const float* __restrict__ bo, float* __restrict__ Y)
{
    gemm_body<0>(g_ctx, g_Wall + (size_t)3 * DM * DM, bo, Y);
}

// ---------------------------------------------------------------------------
// Flash attention, tf32 mma, cp.async double-buffered KV (BKV=32),
// P kept in registers (accumulator->A-operand via shuffles), one sync/iter.
// Block = (b, h, 128-query tile), 256 threads = 8 warps x 16 query rows.
// ---------------------------------------------------------------------------
#define QSS 68
#define KSS 68
#define VSS 72
#define BKV 32
#define ATTN_SMEM_FLOATS (128 * QSS + 2 * BKV * KSS + 2 * BKV * VSS)  // 17664

__global__ __launch_bounds__(256, 2)
void attn_tf32_kernel()
{
    extern __shared__ float sm[];
    float* Qs = sm;                             // [128][QSS]
    float* Ks = Qs + 128 * QSS;                 // [2][BKV][KSS]
    float* Vs = Ks + 2 * BKV * KSS;             // [2][BKV][VSS]

    const int tid  = threadIdx.x;
    const int warp = tid >> 5, lane = tid & 31;
    const int g = lane >> 2, t = lane & 3;
    const int qb = blockIdx.x;
    const int h  = blockIdx.y;
    const int b  = blockIdx.z;

    const size_t head_off = ((size_t)b * HEADS + h) * SEQ * DK;
    const float* Qg = g_Q + head_off + (size_t)qb * 128 * DK;
    const float* Kg = g_K + head_off;
    const float* Vg = g_V + head_off;

    // stage KV tile 0
#pragma unroll
    for (int i = 0; i < 2; i++) {
        const int idx = tid + i * 256;          // 0..511
        const int row = idx >> 4, c4 = (idx & 15) << 2;
        cp16(&Ks[row * KSS + c4], &Kg[(size_t)row * DK + c4]);
        cp16(&Vs[row * VSS + c4], &Vg[(size_t)row * DK + c4]);
    }
    cp_commit();

    // Q tile: scale by 1/sqrt(dk)*log2(e), round to tf32
    const float qscale = 0.125f * 1.4426950408889634f;
#pragma unroll
    for (int i = 0; i < 8; i++) {
        const int idx = tid + i * 256;
        const int row = idx >> 4, c4 = (idx & 15) << 2;
        float4 v = *reinterpret_cast<const float4*>(&Qg[(size_t)row * DK + c4]);
        v.x = to_tf32(v.x * qscale); v.y = to_tf32(v.y * qscale);
        v.z = to_tf32(v.z * qscale); v.w = to_tf32(v.w * qscale);
        *reinterpret_cast<float4*>(&Qs[row * QSS + c4]) = v;
    }

    float O[8][4];
#pragma unroll
    for (int nf = 0; nf < 8; nf++)
#pragma unroll
        for (int j = 0; j < 4; j++) O[nf][j] = 0.f;
    float mrow0 = -INFINITY, mrow1 = -INFINITY;
    float lrow0 = 0.f, lrow1 = 0.f;

    const int qrow = warp * 16;
    const int NT = SEQ / BKV;   // 64

    for (int it = 0; it < NT; it++) {
        const int cur = it & 1;
        cp_wait<0>();
        __syncthreads();   // KV(it) visible; all warps done with buf being reloaded

        if (it + 1 < NT) {
            const int kb = (it + 1) * BKV;
            const int nb = (it + 1) & 1;
#pragma unroll
            for (int i = 0; i < 2; i++) {
                const int idx = tid + i * 256;
                const int row = idx >> 4, c4 = (idx & 15) << 2;
                cp16(&Ks[nb * BKV * KSS + row * KSS + c4], &Kg[(size_t)(kb + row) * DK + c4]);
                cp16(&Vs[nb * BKV * VSS + row * VSS + c4], &Vg[(size_t)(kb + row) * DK + c4]);
            }
            cp_commit();
        }

        const float* Kc = Ks + cur * BKV * KSS;
        const float* Vc = Vs + cur * BKV * VSS;

        // S = Q(16 rows) @ K^T -> s[4][4]
        float s[4][4];
#pragma unroll
        for (int nf = 0; nf < 4; nf++)
#pragma unroll
            for (int j = 0; j < 4; j++) s[nf][j] = 0.f;

#pragma unroll
        for (int kk = 0; kk < 8; kk++) {
            const uint32_t a0 = f2u(Qs[(qrow + g    ) * QSS + kk * 8 + t    ]);
            const uint32_t a1 = f2u(Qs[(qrow + g + 8) * QSS + kk * 8 + t    ]);
            const uint32_t a2 = f2u(Qs[(qrow + g    ) * QSS + kk * 8 + t + 4]);
            const uint32_t a3 = f2u(Qs[(qrow + g + 8) * QSS + kk * 8 + t + 4]);
#pragma unroll
            for (int nf = 0; nf < 4; nf++) {
                const uint32_t b0 = f2u(Kc[(nf * 8 + g) * KSS + kk * 8 + t    ]);
                const uint32_t b1 = f2u(Kc[(nf * 8 + g) * KSS + kk * 8 + t + 4]);
                mma_m16n8k8(s[nf], a0, a1, a2, a3, b0, b1);
            }
        }

        // online softmax (rows qrow+g, qrow+g+8)
        float ml0 = -INFINITY, ml1 = -INFINITY;
#pragma unroll
        for (int nf = 0; nf < 4; nf++) {
            ml0 = fmaxf(ml0, fmaxf(s[nf][0], s[nf][1]));
            ml1 = fmaxf(ml1, fmaxf(s[nf][2], s[nf][3]));
        }
        ml0 = fmaxf(ml0, __shfl_xor_sync(0xffffffffu, ml0, 1));
        ml0 = fmaxf(ml0, __shfl_xor_sync(0xffffffffu, ml0, 2));
        ml1 = fmaxf(ml1, __shfl_xor_sync(0xffffffffu, ml1, 1));
        ml1 = fmaxf(ml1, __shfl_xor_sync(0xffffffffu, ml1, 2));
        const float mn0 = fmaxf(mrow0, ml0);
        const float mn1 = fmaxf(mrow1, ml1);
        const float alpha0 = ex2f_(mrow0 - mn0);
        const float alpha1 = ex2f_(mrow1 - mn1);

        float rs0 = 0.f, rs1 = 0.f;
#pragma unroll
        for (int nf = 0; nf < 4; nf++) {
            s[nf][0] = to_tf32(ex2f_(s[nf][0] - mn0));
            s[nf][1] = to_tf32(ex2f_(s[nf][1] - mn0));
            s[nf][2] = to_tf32(ex2f_(s[nf][2] - mn1));
            s[nf][3] = to_tf32(ex2f_(s[nf][3] - mn1));
            rs0 += s[nf][0] + s[nf][1];
            rs1 += s[nf][2] + s[nf][3];
        }
        rs0 += __shfl_xor_sync(0xffffffffu, rs0, 1);
        rs0 += __shfl_xor_sync(0xffffffffu, rs0, 2);
        rs1 += __shfl_xor_sync(0xffffffffu, rs1, 1);
        rs1 += __shfl_xor_sync(0xffffffffu, rs1, 2);

        if (__any_sync(0xffffffffu, (alpha0 < 1.f) | (alpha1 < 1.f))) {
#pragma unroll
            for (int nf = 0; nf < 8; nf++) {
                O[nf][0] *= alpha0; O[nf][1] *= alpha0;
                O[nf][2] *= alpha1; O[nf][3] *= alpha1;
            }
        }
        lrow0 = lrow0 * alpha0 + rs0;
        lrow1 = lrow1 * alpha1 + rs1;
        mrow0 = mn0; mrow1 = mn1;

        // O += P @ V : accumulator frags -> A frags via shuffles
#pragma unroll
        for (int kk = 0; kk < 4; kk++) {
            const int srcA = (lane & ~3) | (t >> 1);
            const float v0 = __shfl_sync(0xffffffffu, s[kk][0], srcA);
            const float v1 = __shfl_sync(0xffffffffu, s[kk][1], srcA);
            const float v2 = __shfl_sync(0xffffffffu, s[kk][2], srcA);
            const float v3 = __shfl_sync(0xffffffffu, s[kk][3], srcA);
            const float w0 = __shfl_sync(0xffffffffu, s[kk][0], srcA + 2);
            const float w1 = __shfl_sync(0xffffffffu, s[kk][1], srcA + 2);
            const float w2 = __shfl_sync(0xffffffffu, s[kk][2], srcA + 2);
            const float w3 = __shfl_sync(0xffffffffu, s[kk][3], srcA + 2);
            const bool odd = t & 1;
            const uint32_t a0 = f2u(odd ? v1 : v0);
            const uint32_t a1 = f2u(odd ? v3 : v2);
            const uint32_t a2 = f2u(odd ? w1 : w0);
            const uint32_t a3 = f2u(odd ? w3 : w2);
#pragma unroll
            for (int nf = 0; nf < 8; nf++) {
                const uint32_t b0 = f2u(Vc[(kk * 8 + t    ) * VSS + nf * 8 + g]);
                const uint32_t b1 = f2u(Vc[(kk * 8 + t + 4) * VSS + nf * 8 + g]);
                mma_m16n8k8(O[nf], a0, a1, a2, a3, b0, b1);
            }
        }
    }

    // epilogue: normalize, round to tf32 (feeds out-proj), write [B,T,DM]
    const float inv0 = 1.f / lrow0;
    const float inv1 = 1.f / lrow1;
    const int t0 = qb * 128 + qrow + g;
#pragma unroll
    for (int nf = 0; nf < 8; nf++) {
        const int d = h * DK + nf * 8 + 2 * t;
        float2 lo = make_float2(to_tf32(O[nf][0] * inv0), to_tf32(O[nf][1] * inv0));
        float2 hi = make_float2(to_tf32(O[nf][2] * inv1), to_tf32(O[nf][3] * inv1));
        *reinterpret_cast<float2*>(&g_ctx[((size_t)b * SEQ + t0    ) * DM + d]) = lo;
        *reinterpret_cast<float2*>(&g_ctx[((size_t)b * SEQ + t0 + 8) * DM + d]) = hi;
    }
}

// ---------------------------------------------------------------------------
// Launch. Inputs: x, W_q, b_q, W_k, b_k, W_v, b_v, W_out, b_out
// ---------------------------------------------------------------------------
extern "C" void kernel_launch(void* const* d_in, const int* in_sizes, int n_in,
                              void* d_out, int out_size)
{
    const float* x   = (const float*)d_in[0];
    const float* W_q = (const float*)d_in[1];
    const float* b_q = (const float*)d_in[2];
    const float* W_k = (const float*)d_in[3];
    const float* b_k = (const float*)d_in[4];
    const float* W_v = (const float*)d_in[5];
    const float* b_v = (const float*)d_in[6];
    const float* W_o = (const float*)d_in[7];
    const float* b_o = (const float*)d_in[8];

    const int gemm_smem = 2 * 2 * 128 * GTS * sizeof(float);        // 73728
    const int attn_smem = ATTN_SMEM_FLOATS * sizeof(float);         // 70656
    cudaFuncSetAttribute(gemm_qkv_kernel,
                         cudaFuncAttributeMaxDynamicSharedMemorySize, gemm_smem);
    cudaFuncSetAttribute(gemm_out_kernel,
                         cudaFuncAttributeMaxDynamicSharedMemorySize, gemm_smem);
    cudaFuncSetAttribute(attn_tf32_kernel,
                         cudaFuncAttributeMaxDynamicSharedMemorySize, attn_smem);

    prepass_kernel<<<(MROWS * DM / 4 + 255) / 256, 256>>>(
        (const float4*)x, (const float4*)W_q, (const float4*)W_k,
        (const float4*)W_v, (const float4*)W_o);

    gemm_qkv_kernel<<<dim3(DM / 128, MROWS / 128, 3), 256, gemm_smem>>>(b_q, b_k, b_v);

    attn_tf32_kernel<<<dim3(SEQ / 128, HEADS, BATCH), 256, attn_smem>>>();

    gemm_out_kernel<<<dim3(DM / 128, MROWS / 128, 1), 256, gemm_smem>>>(b_o, (float*)d_out);
}

// round 4
// speedup vs baseline: 3.9363x; 1.0032x over previous
#include <cuda_runtime.h>
#include <math.h>
#include <stdint.h>

// Problem constants
#define BATCH 2
#define SEQ   2048
#define HEADS 16
#define DK    64
#define DM    1024
#define MROWS (BATCH * SEQ)   // 4096

// Scratch (device globals — no allocation allowed)
// NOTE: g_X and g_Wall are stored with the k-dim RIFFLED within each 8-group:
// position p(k) = ((k&3)<<1)|(k>>2). Dot products over k are invariant.
__device__ float g_X[MROWS * DM];
__device__ float g_Wall[4 * DM * DM];
__device__ float g_Q[BATCH * HEADS * SEQ * DK];   // dk riffled
__device__ float g_K[BATCH * HEADS * SEQ * DK];   // dk riffled
__device__ float g_V[BATCH * HEADS * SEQ * DK];   // dk natural
__device__ float g_ctx[MROWS * DM];               // features riffled (matches Wo)

__device__ __forceinline__ float to_tf32(float x) {
    float y;
    asm("cvt.rna.tf32.f32 %0, %1;" : "=f"(y) : "f"(x));
    return y;
}
__device__ __forceinline__ uint32_t f2u(float x) { return __float_as_uint(x); }

__device__ __forceinline__ float ex2f_(float x) {
    float y;
    asm("ex2.approx.ftz.f32 %0, %1;" : "=f"(y) : "f"(x));
    return y;
}

__device__ __forceinline__ void mma_m16n8k8(float c[4],
    uint32_t a0, uint32_t a1, uint32_t a2, uint32_t a3,
    uint32_t b0, uint32_t b1)
{
    asm volatile(
        "mma.sync.aligned.m16n8k8.row.col.f32.tf32.tf32.f32 "
        "{%0,%1,%2,%3}, {%4,%5,%6,%7}, {%8,%9}, {%0,%1,%2,%3};\n"
        : "+f"(c[0]), "+f"(c[1]), "+f"(c[2]), "+f"(c[3])
        : "r"(a0), "r"(a1), "r"(a2), "r"(a3), "r"(b0), "r"(b1));
}

__device__ __forceinline__ void cp16(float* smem_dst, const float* gsrc) {
    uint32_t s = (uint32_t)__cvta_generic_to_shared(smem_dst);
    asm volatile("cp.async.cg.shared.global [%0], [%1], 16;\n" :: "r"(s), "l"(gsrc));
}
__device__ __forceinline__ void cp_commit() {
    asm volatile("cp.async.commit_group;\n");
}
template <int N>
__device__ __forceinline__ void cp_wait() {
    asm volatile("cp.async.wait_group %0;\n" :: "n"(N));
}

// riffle one 8-group: out = {in0,in4,in1,in5,in2,in6,in3,in7}, tf32-rounded
__device__ __forceinline__ void riffle8(const float4* __restrict__ src,
                                        float4* __restrict__ dst)
{
    const float4 lo = src[0], hi = src[1];
    dst[0] = make_float4(to_tf32(lo.x), to_tf32(hi.x), to_tf32(lo.y), to_tf32(hi.y));
    dst[1] = make_float4(to_tf32(lo.z), to_tf32(hi.z), to_tf32(lo.w), to_tf32(hi.w));
}

// ---------------------------------------------------------------------------
// Prepass: riffle+tf32-round x and the 4 weight matrices (k-dim groups of 8).
// ---------------------------------------------------------------------------
__global__ void prepass_kernel(const float4* __restrict__ x,
                               const float4* __restrict__ wq,
                               const float4* __restrict__ wk,
                               const float4* __restrict__ wv,
                               const float4* __restrict__ wo)
{
    const int i = blockIdx.x * blockDim.x + threadIdx.x;   // 8-float group index
    float4* X4 = reinterpret_cast<float4*>(g_X);
    float4* W4 = reinterpret_cast<float4*>(g_Wall);
    if (i < MROWS * DM / 8)
        riffle8(&x[2 * i], &X4[2 * i]);
    if (i < DM * DM / 8) {
        const int WQ = DM * DM / 4;
        riffle8(&wq[2 * i], &W4[2 * i]);
        riffle8(&wk[2 * i], &W4[2 * i + WQ]);
        riffle8(&wv[2 * i], &W4[2 * i + 2 * WQ]);
        riffle8(&wo[2 * i], &W4[2 * i + 3 * WQ]);
    }
}

// ---------------------------------------------------------------------------
// tf32 GEMM: Y = X @ W^T + bias. X:[4096,1024] riffled-k, W:[1024,1024] riffled-k.
// 128x128 tile, BK=32, cp.async double buffer, fragment loads are LDS.64
// (riffled pairs), smem stride 40 (==8 mod 32) => conflict-free 64-bit LDS.
// MODE 0: plain [M,N]. MODE 1: scatter [B,H,T,dk], dk riffled (Q,K).
// MODE 2: scatter [B,H,T,dk], natural (V).
// ---------------------------------------------------------------------------
#define GTS 40

template <int MODE>
__device__ __forceinline__ void gemm_body(const float* __restrict__ X,
                                          const float* __restrict__ W,
                                          const float* __restrict__ bias,
                                          float* __restrict__ Y)
{
    extern __shared__ float sm[];
    float* Xs = sm;                      // [2][128*GTS]
    float* Ws = sm + 2 * 128 * GTS;

    const int tid  = threadIdx.x;
    const int warp = tid >> 5, lane = tid & 31;
    const int g = lane >> 2, t = lane & 3;
    const int wm = warp >> 1;            // 0..3
    const int wn = warp & 1;             // 0..1
    const int m0 = blockIdx.y * 128;
    const int n0 = blockIdx.x * 128;

    float acc[2][8][4];
#pragma unroll
    for (int mf = 0; mf < 2; mf++)
#pragma unroll
        for (int nf = 0; nf < 8; nf++)
#pragma unroll
            for (int j = 0; j < 4; j++) acc[mf][nf][j] = 0.f;

    const int NKB = DM / 32;  // 32

#pragma unroll
    for (int i = 0; i < 4; i++) {
        const int idx = tid + i * 256;
        const int row = idx >> 3, c4 = (idx & 7) << 2;
        cp16(&Xs[row * GTS + c4], &X[(size_t)(m0 + row) * DM + c4]);
        cp16(&Ws[row * GTS + c4], &W[(size_t)(n0 + row) * DM + c4]);
    }
    cp_commit();

    for (int kb = 0; kb < NKB; kb++) {
        const int cur = kb & 1;
        cp_wait<0>();
        __syncthreads();

        if (kb + 1 < NKB) {
            const int k0 = (kb + 1) * 32;
            const int nb = (kb + 1) & 1;
#pragma unroll
            for (int i = 0; i < 4; i++) {
                const int idx = tid + i * 256;
                const int row = idx >> 3, c4 = (idx & 7) << 2;
                cp16(&Xs[nb * 128 * GTS + row * GTS + c4],
                     &X[(size_t)(m0 + row) * DM + k0 + c4]);
                cp16(&Ws[nb * 128 * GTS + row * GTS + c4],
                     &W[(size_t)(n0 + row) * DM + k0 + c4]);
            }
            cp_commit();
        }

        const float* Xc = Xs + cur * 128 * GTS;
        const float* Wc = Ws + cur * 128 * GTS;
#pragma unroll
        for (int kk = 0; kk < 4; kk++) {
            const int ko = kk * 8 + 2 * t;
            float2 aLo[2], aHi[2];
#pragma unroll
            for (int mf = 0; mf < 2; mf++) {
                const int r = wm * 32 + mf * 16;
                aLo[mf] = *reinterpret_cast<const float2*>(&Xc[(r + g    ) * GTS + ko]);
                aHi[mf] = *reinterpret_cast<const float2*>(&Xc[(r + g + 8) * GTS + ko]);
            }
#pragma unroll
            for (int nf = 0; nf < 8; nf++) {
                const float2 bb =
                    *reinterpret_cast<const float2*>(&Wc[(wn * 64 + nf * 8 + g) * GTS + ko]);
#pragma unroll
                for (int mf = 0; mf < 2; mf++)
                    mma_m16n8k8(acc[mf][nf],
                                f2u(aLo[mf].x), f2u(aHi[mf].x),
                                f2u(aLo[mf].y), f2u(aHi[mf].y),
                                f2u(bb.x), f2u(bb.y));
            }
        }
    }

    // Epilogue.  c-frag cols (2t, 2t+1); riffled positions (c0, c0+2).
    const int c0 = ((2 * t & 3) << 1) | (t >> 1);   // p(2t)
#pragma unroll
    for (int mf = 0; mf < 2; mf++) {
        const int m = m0 + wm * 32 + mf * 16 + g;
#pragma unroll
        for (int nf = 0; nf < 8; nf++) {
            const int n = n0 + wn * 64 + nf * 8 + 2 * t;
            const float bn0 = bias[n], bn1 = bias[n + 1];
            if (MODE == 0) {
                float2 lo = make_float2(acc[mf][nf][0] + bn0, acc[mf][nf][1] + bn1);
                float2 hi = make_float2(acc[mf][nf][2] + bn0, acc[mf][nf][3] + bn1);
                *reinterpret_cast<float2*>(&Y[(size_t)m * DM + n]) = lo;
                *reinterpret_cast<float2*>(&Y[(size_t)(m + 8) * DM + n]) = hi;
            } else {
                const int nb_ = n0 + wn * 64 + nf * 8;        // group base (natural)
                const int h_  = nb_ / DK;
                const int db_ = nb_ % DK;
                const int b0_ = m / SEQ, t0_ = m % SEQ;
                const int b1_ = (m + 8) / SEQ, t1_ = (m + 8) % SEQ;
                float* y0 = &Y[((((size_t)b0_ * HEADS + h_) * SEQ) + t0_) * DK + db_];
                float* y1 = &Y[((((size_t)b1_ * HEADS + h_) * SEQ) + t1_) * DK + db_];
                const float v00 = to_tf32(acc[mf][nf][0] + bn0);
                const float v01 = to_tf32(acc[mf][nf][1] + bn1);
                const float v10 = to_tf32(acc[mf][nf][2] + bn0);
                const float v11 = to_tf32(acc[mf][nf][3] + bn1);
                if (MODE == 1) {      // riffled dk positions
                    y0[c0] = v00; y0[c0 + 2] = v01;
                    y1[c0] = v10; y1[c0 + 2] = v11;
                } else {              // natural (V)
                    *reinterpret_cast<float2*>(&y0[2 * t]) = make_float2(v00, v01);
                    *reinterpret_cast<float2*>(&y1[2 * t]) = make_float2(v10, v11);
                }
            }
        }
    }
}

__global__ __launch_bounds__(256, 2)
void gemm_qkv_kernel(const float* __restrict__ bq,
                     const float* __restrict__ bk,
                     const float* __restrict__ bv)
{
    const int z = blockIdx.z;
    const float* W    = g_Wall + (size_t)z * DM * DM;
    if (z == 0)      gemm_body<1>(g_X, W, bq, g_Q);
    else if (z == 1) gemm_body<1>(g_X, W, bk, g_K);
    else             gemm_body<2>(g_X, W, bv, g_V);
}

__global__ __launch_bounds__(256, 2)
void gemm_out_kernel(const float* __restrict__ bo, float* __restrict__ Y)
{
    gemm_body<0>(g_ctx, g_Wall + (size_t)3 * DM * DM, bo, Y);
}

// ---------------------------------------------------------------------------
// Flash attention, tf32 mma. Q/K dk-riffled => QK frags are LDS.64.
// cp.async double-buffered KV (BKV=32), P in registers via shuffles.
// Strides 72 (==8 mod 32): conflict-free for paired and V-pattern loads.
// ---------------------------------------------------------------------------
#define QSS 72
#define KSS 72
#define VSS 72
#define BKV 32
#define ATTN_SMEM_FLOATS (128 * QSS + 2 * BKV * KSS + 2 * BKV * VSS)

__global__ __launch_bounds__(256, 2)
void attn_tf32_kernel()
{
    extern __shared__ float sm[];
    float* Qs = sm;                             // [128][QSS]
    float* Ks = Qs + 128 * QSS;                 // [2][BKV][KSS]
    float* Vs = Ks + 2 * BKV * KSS;             // [2][BKV][VSS]

    const int tid  = threadIdx.x;
    const int warp = tid >> 5, lane = tid & 31;
    const int g = lane >> 2, t = lane & 3;
    const int qb = blockIdx.x;
    const int h  = blockIdx.y;
    const int b  = blockIdx.z;

    const size_t head_off = ((size_t)b * HEADS + h) * SEQ * DK;
    const float* Qg = g_Q + head_off + (size_t)qb * 128 * DK;
    const float* Kg = g_K + head_off;
    const float* Vg = g_V + head_off;

#pragma unroll
    for (int i = 0; i < 2; i++) {
        const int idx = tid + i * 256;
        const int row = idx >> 4, c4 = (idx & 15) << 2;
        cp16(&Ks[row * KSS + c4], &Kg[(size_t)row * DK + c4]);
        cp16(&Vs[row * VSS + c4], &Vg[(size_t)row * DK + c4]);
    }
    cp_commit();

    const float qscale = 0.125f * 1.4426950408889634f;
#pragma unroll
    for (int i = 0; i < 8; i++) {
        const int idx = tid + i * 256;
        const int row = idx >> 4, c4 = (idx & 15) << 2;
        float4 v = *reinterpret_cast<const float4*>(&Qg[(size_t)row * DK + c4]);
        v.x = to_tf32(v.x * qscale); v.y = to_tf32(v.y * qscale);
        v.z = to_tf32(v.z * qscale); v.w = to_tf32(v.w * qscale);
        *reinterpret_cast<float4*>(&Qs[row * QSS + c4]) = v;
    }

    float O[8][4];
#pragma unroll
    for (int nf = 0; nf < 8; nf++)
#pragma unroll
        for (int j = 0; j < 4; j++) O[nf][j] = 0.f;
    float mrow0 = -INFINITY, mrow1 = -INFINITY;
    float lrow0 = 0.f, lrow1 = 0.f;

    const int qrow = warp * 16;
    const int NT = SEQ / BKV;   // 64

    for (int it = 0; it < NT; it++) {
        const int cur = it & 1;
        cp_wait<0>();
        __syncthreads();

        if (it + 1 < NT) {
            const int kb = (it + 1) * BKV;
            const int nb = (it + 1) & 1;
#pragma unroll
            for (int i = 0; i < 2; i++) {
                const int idx = tid + i * 256;
                const int row = idx >> 4, c4 = (idx & 15) << 2;
                cp16(&Ks[nb * BKV * KSS + row * KSS + c4], &Kg[(size_t)(kb + row) * DK + c4]);
                cp16(&Vs[nb * BKV * VSS + row * VSS + c4], &Vg[(size_t)(kb + row) * DK + c4]);
            }
            cp_commit();
        }

        const float* Kc = Ks + cur * BKV * KSS;
        const float* Vc = Vs + cur * BKV * VSS;

        // S = Q @ K^T   (dk riffled: paired LDS.64 frags)
        float s[4][4];
#pragma unroll
        for (int nf = 0; nf < 4; nf++)
#pragma unroll
            for (int j = 0; j < 4; j++) s[nf][j] = 0.f;

#pragma unroll
        for (int kk = 0; kk < 8; kk++) {
            const int ko = kk * 8 + 2 * t;
            const float2 aLo = *reinterpret_cast<const float2*>(&Qs[(qrow + g    ) * QSS + ko]);
            const float2 aHi = *reinterpret_cast<const float2*>(&Qs[(qrow + g + 8) * QSS + ko]);
#pragma unroll
            for (int nf = 0; nf < 4; nf++) {
                const float2 bb = *reinterpret_cast<const float2*>(&Kc[(nf * 8 + g) * KSS + ko]);
                mma_m16n8k8(s[nf], f2u(aLo.x), f2u(aHi.x), f2u(aLo.y), f2u(aHi.y),
                            f2u(bb.x), f2u(bb.y));
            }
        }

        // online softmax (rows qrow+g, qrow+g+8)
        float ml0 = -INFINITY, ml1 = -INFINITY;
#pragma unroll
        for (int nf = 0; nf < 4; nf++) {
            ml0 = fmaxf(ml0, fmaxf(s[nf][0], s[nf][1]));
            ml1 = fmaxf(ml1, fmaxf(s[nf][2], s[nf][3]));
        }
        ml0 = fmaxf(ml0, __shfl_xor_sync(0xffffffffu, ml0, 1));
        ml0 = fmaxf(ml0, __shfl_xor_sync(0xffffffffu, ml0, 2));
        ml1 = fmaxf(ml1, __shfl_xor_sync(0xffffffffu, ml1, 1));
        ml1 = fmaxf(ml1, __shfl_xor_sync(0xffffffffu, ml1, 2));
        const float mn0 = fmaxf(mrow0, ml0);
        const float mn1 = fmaxf(mrow1, ml1);
        const float alpha0 = ex2f_(mrow0 - mn0);
        const float alpha1 = ex2f_(mrow1 - mn1);

        float rs0 = 0.f, rs1 = 0.f;
#pragma unroll
        for (int nf = 0; nf < 4; nf++) {
            s[nf][0] = to_tf32(ex2f_(s[nf][0] - mn0));
            s[nf][1] = to_tf32(ex2f_(s[nf][1] - mn0));
            s[nf][2] = to_tf32(ex2f_(s[nf][2] - mn1));
            s[nf][3] = to_tf32(ex2f_(s[nf][3] - mn1));
            rs0 += s[nf][0] + s[nf][1];
            rs1 += s[nf][2] + s[nf][3];
        }
        rs0 += __shfl_xor_sync(0xffffffffu, rs0, 1);
        rs0 += __shfl_xor_sync(0xffffffffu, rs0, 2);
        rs1 += __shfl_xor_sync(0xffffffffu, rs1, 1);
        rs1 += __shfl_xor_sync(0xffffffffu, rs1, 2);

        if (__any_sync(0xffffffffu, (alpha0 < 1.f) | (alpha1 < 1.f))) {
#pragma unroll
            for (int nf = 0; nf < 8; nf++) {
                O[nf][0] *= alpha0; O[nf][1] *= alpha0;
                O[nf][2] *= alpha1; O[nf][3] *= alpha1;
            }
        }
        lrow0 = lrow0 * alpha0 + rs0;
        lrow1 = lrow1 * alpha1 + rs1;
        mrow0 = mn0; mrow1 = mn1;

        // O += P @ V  (P frags via shuffles; V natural layout)
#pragma unroll
        for (int kk = 0; kk < 4; kk++) {
            const int srcA = (lane & ~3) | (t >> 1);
            const float v0 = __shfl_sync(0xffffffffu, s[kk][0], srcA);
            const float v1 = __shfl_sync(0xffffffffu, s[kk][1], srcA);
            const float v2 = __shfl_sync(0xffffffffu, s[kk][2], srcA);
            const float v3 = __shfl_sync(0xffffffffu, s[kk][3], srcA);
            const float w0 = __shfl_sync(0xffffffffu, s[kk][0], srcA + 2);
            const float w1 = __shfl_sync(0xffffffffu, s[kk][1], srcA + 2);
            const float w2 = __shfl_sync(0xffffffffu, s[kk][2], srcA + 2);
            const float w3 = __shfl_sync(0xffffffffu, s[kk][3], srcA + 2);
            const bool odd = t & 1;
            const uint32_t a0 = f2u(odd ? v1 : v0);
            const uint32_t a1 = f2u(odd ? v3 : v2);
            const uint32_t a2 = f2u(odd ? w1 : w0);
            const uint32_t a3 = f2u(odd ? w3 : w2);
#pragma unroll
            for (int nf = 0; nf < 8; nf++) {
                const uint32_t b0 = f2u(Vc[(kk * 8 + t    ) * VSS + nf * 8 + g]);
                const uint32_t b1 = f2u(Vc[(kk * 8 + t + 4) * VSS + nf * 8 + g]);
                mma_m16n8k8(O[nf], a0, a1, a2, a3, b0, b1);
            }
        }
    }

    // Epilogue: normalize, write ctx riffled in feature dim (matches Wo).
    const float inv0 = 1.f / lrow0;
    const float inv1 = 1.f / lrow1;
    const int t0 = qb * 128 + qrow + g;
    const int c0 = ((2 * t & 3) << 1) | (t >> 1);   // p(2t)
#pragma unroll
    for (int nf = 0; nf < 8; nf++) {
        const int dbase = h * DK + nf * 8;
        float* r0 = &g_ctx[((size_t)b * SEQ + t0    ) * DM + dbase];
        float* r1 = &g_ctx[((size_t)b * SEQ + t0 + 8) * DM + dbase];
        r0[c0]     = to_tf32(O[nf][0] * inv0);
        r0[c0 + 2] = to_tf32(O[nf][1] * inv0);
        r1[c0]     = to_tf32(O[nf][2] * inv1);
        r1[c0 + 2] = to_tf32(O[nf][3] * inv1);
    }
}

// ---------------------------------------------------------------------------
// Launch. Inputs: x, W_q, b_q, W_k, b_k, W_v, b_v, W_out, b_out
// ---------------------------------------------------------------------------
extern "C" void kernel_launch(void* const* d_in, const int* in_sizes, int n_in,
                              void* d_out, int out_size)
{
    const float* x   = (const float*)d_in[0];
    const float* W_q = (const float*)d_in[1];
    const float* b_q = (const float*)d_in[2];
    const float* W_k = (const float*)d_in[3];
    const float* b_k = (const float*)d_in[4];
    const float* W_v = (const float*)d_in[5];
    const float* b_v = (const float*)d_in[6];
    const float* W_o = (const float*)d_in[7];
    const float* b_o = (const float*)d_in[8];

    const int gemm_smem = 2 * 2 * 128 * GTS * sizeof(float);   // 81920
    const int attn_smem = ATTN_SMEM_FLOATS * sizeof(float);    // 55296
    cudaFuncSetAttribute(gemm_qkv_kernel,
                         cudaFuncAttributeMaxDynamicSharedMemorySize, gemm_smem);
    cudaFuncSetAttribute(gemm_out_kernel,
                         cudaFuncAttributeMaxDynamicSharedMemorySize, gemm_smem);
    cudaFuncSetAttribute(attn_tf32_kernel,
                         cudaFuncAttributeMaxDynamicSharedMemorySize, attn_smem);

    prepass_kernel<<<(MROWS * DM / 8 + 255) / 256, 256>>>(
        (const float4*)x, (const float4*)W_q, (const float4*)W_k,
        (const float4*)W_v, (const float4*)W_o);

    gemm_qkv_kernel<<<dim3(DM / 128, MROWS / 128, 3), 256, gemm_smem>>>(b_q, b_k, b_v);

    attn_tf32_kernel<<<dim3(SEQ / 128, HEADS, BATCH), 256, attn_smem>>>();

    gemm_out_kernel<<<dim3(DM / 128, MROWS / 128, 1), 256, gemm_smem>>>(b_o, (float*)d_out);
}

// round 6
// speedup vs baseline: 7.5550x; 1.9193x over previous
#include <cuda_runtime.h>
#include <cuda_fp16.h>
#include <math.h>
#include <stdint.h>

// Problem constants
#define BATCH 2
#define SEQ   2048
#define HEADS 16
#define DK    64
#define DM    1024
#define MROWS (BATCH * SEQ)   // 4096

// Scratch (device globals — no allocation allowed).
// All half tensors keep the contraction dim PERMUTED within 16-groups:
// stored order [0,1,8,9, 2,3,10,11, 4,5,12,13, 6,7,14,15], so an fp16 mma
// fragment's k-pair regs {(2t,2t+1),(2t+8,2t+9)} are 4 contiguous halves.
// Contractions are permutation-invariant (both operands share the perm).
__device__ __half g_X[MROWS * DM];                  // k(=feature) permuted
__device__ __half g_Wall[4 * DM * DM];              // k permuted, rows natural
__device__ __half g_Q[BATCH * HEADS * SEQ * DK];    // dk permuted, pre-scaled
__device__ __half g_K[BATCH * HEADS * SEQ * DK];    // dk permuted
__device__ __half g_V[BATCH * HEADS * DK * SEQ];    // TRANSPOSED [B,H,dk,T]
__device__ __half g_ctx[MROWS * DM];                // feature permuted (matches Wo)

__device__ __forceinline__ uint32_t f2h2(float a, float b) {
    __half2 h = __floats2half2_rn(a, b);
    return *reinterpret_cast<uint32_t*>(&h);
}
__device__ __forceinline__ float ex2f_(float x) {
    float y;
    asm("ex2.approx.ftz.f32 %0, %1;" : "=f"(y) : "f"(x));
    return y;
}

// fp16 mma: D(16x8,f32) += A(16x16,f16) * B(16x8,f16)
__device__ __forceinline__ void mma_f16(float c[4],
    uint32_t a0, uint32_t a1, uint32_t a2, uint32_t a3,
    uint32_t b0, uint32_t b1)
{
    asm volatile(
        "mma.sync.aligned.m16n8k16.row.col.f32.f16.f16.f32 "
        "{%0,%1,%2,%3}, {%4,%5,%6,%7}, {%8,%9}, {%0,%1,%2,%3};\n"
        : "+f"(c[0]), "+f"(c[1]), "+f"(c[2]), "+f"(c[3])
        : "r"(a0), "r"(a1), "r"(a2), "r"(a3), "r"(b0), "r"(b1));
}

__device__ __forceinline__ void cp16h(__half* smem_dst, const __half* gsrc) {
    uint32_t s = (uint32_t)__cvta_generic_to_shared(smem_dst);
    asm volatile("cp.async.cg.shared.global [%0], [%1], 16;\n" :: "r"(s), "l"(gsrc));
}
__device__ __forceinline__ void cp_commit() {
    asm volatile("cp.async.commit_group;\n");
}
template <int N>
__device__ __forceinline__ void cp_wait() {
    asm volatile("cp.async.wait_group %0;\n" :: "n"(N));
}

// ---------------------------------------------------------------------------
// Prepass: fp32 -> fp16 with 16-group k-permutation.
// For each natural 16-group (v0..v3 = 16 floats), stored half order is:
// {0,1,8,9, 2,3,10,11, 4,5,12,13, 6,7,14,15}.
// ---------------------------------------------------------------------------
__device__ __forceinline__ void perm16(const float4* __restrict__ src,
                                       uint32_t* __restrict__ dst)   // 8 words
{
    const float4 v0 = src[0], v1 = src[1], v2 = src[2], v3 = src[3];
    dst[0] = f2h2(v0.x, v0.y);  dst[1] = f2h2(v2.x, v2.y);
    dst[2] = f2h2(v0.z, v0.w);  dst[3] = f2h2(v2.z, v2.w);
    dst[4] = f2h2(v1.x, v1.y);  dst[5] = f2h2(v3.x, v3.y);
    dst[6] = f2h2(v1.z, v1.w);  dst[7] = f2h2(v3.z, v3.w);
}

__global__ void prepass_kernel(const float4* __restrict__ x,
                               const float4* __restrict__ wq,
                               const float4* __restrict__ wk,
                               const float4* __restrict__ wv,
                               const float4* __restrict__ wo)
{
    const int i = blockIdx.x * blockDim.x + threadIdx.x;   // 16-float group idx
    uint32_t* X2 = reinterpret_cast<uint32_t*>(g_X);
    uint32_t* W2 = reinterpret_cast<uint32_t*>(g_Wall);
    if (i < MROWS * DM / 16)
        perm16(&x[4 * i], &X2[8 * i]);
    if (i < DM * DM / 16) {
        const int WQ = DM * DM / 2;   // uint32 words per matrix
        perm16(&wq[4 * i], &W2[8 * i]);
        perm16(&wk[4 * i], &W2[8 * i + WQ]);
        perm16(&wv[4 * i], &W2[8 * i + 2 * WQ]);
        perm16(&wo[4 * i], &W2[8 * i + 3 * WQ]);
    }
}

// ---------------------------------------------------------------------------
// fp16 GEMM: Y = X @ W^T + bias.  X:[4096,1024] half k-perm, W:[1024,1024].
// 128x128 tile, BK=64, cp.async double buffer, one syncthreads per chunk.
// 8 warps 4(M)x2(N), warp tile 32x64, m16n8k16.
// MODE 0: fp32 [M,N] natural.  MODE 1: half scatter [B,H,T,dk] dk-perm (Q,K;
// scaled by scl).  MODE 2: half scatter TRANSPOSED [B,H,dk,T] natural (V).
// smem stride 80 halves (160B): LDS.64 fragment pattern conflict-free.
// ---------------------------------------------------------------------------
#define GTS 80   // halves per smem row
#define GEMM_SMEM_BYTES (4 * 128 * GTS * 2)   // 2 bufs x (X+W) = 81920

template <int MODE>
__device__ __forceinline__ void gemm_body(const __half* __restrict__ X,
                                          const __half* __restrict__ W,
                                          const float* __restrict__ bias,
                                          void* __restrict__ Yv,
                                          float scl)
{
    extern __shared__ __half smh[];
    __half* Xs = smh;                       // [2][128*GTS]
    __half* Ws = smh + 2 * 128 * GTS;

    const int tid  = threadIdx.x;
    const int warp = tid >> 5, lane = tid & 31;
    const int g = lane >> 2, t = lane & 3;
    const int wm = warp >> 1;               // 0..3
    const int wn = warp & 1;                // 0..1
    const int m0 = blockIdx.y * 128;
    const int n0 = blockIdx.x * 128;

    float acc[2][8][4];
#pragma unroll
    for (int mf = 0; mf < 2; mf++)
#pragma unroll
        for (int nf = 0; nf < 8; nf++)
#pragma unroll
            for (int j = 0; j < 4; j++) acc[mf][nf][j] = 0.f;

    const int NKB = DM / 64;   // 16

    // stage chunk 0 (X: 1024 x16B chunks, W: 1024) — 8 per thread
#pragma unroll
    for (int i = 0; i < 4; i++) {
        const int idx = tid + i * 256;
        const int row = idx >> 3, c8 = (idx & 7) << 3;   // 8 halves per chunk
        cp16h(&Xs[row * GTS + c8], &X[(size_t)(m0 + row) * DM + c8]);
        cp16h(&Ws[row * GTS + c8], &W[(size_t)(n0 + row) * DM + c8]);
    }
    cp_commit();

    for (int kb = 0; kb < NKB; kb++) {
        const int cur = kb & 1;
        cp_wait<0>();
        __syncthreads();

        if (kb + 1 < NKB) {
            const int k0 = (kb + 1) * 64;
            const int nb = (kb + 1) & 1;
#pragma unroll
            for (int i = 0; i < 4; i++) {
                const int idx = tid + i * 256;
                const int row = idx >> 3, c8 = (idx & 7) << 3;
                cp16h(&Xs[nb * 128 * GTS + row * GTS + c8],
                      &X[(size_t)(m0 + row) * DM + k0 + c8]);
                cp16h(&Ws[nb * 128 * GTS + row * GTS + c8],
                      &W[(size_t)(n0 + row) * DM + k0 + c8]);
            }
            cp_commit();
        }

        const __half* Xc = Xs + cur * 128 * GTS;
        const __half* Wc = Ws + cur * 128 * GTS;
#pragma unroll
        for (int kk = 0; kk < 4; kk++) {
            const int ko = kk * 16 + 4 * t;   // halves: {2t,2t+1,2t+8,2t+9}
            uint2 aL[2], aH[2];
#pragma unroll
            for (int mf = 0; mf < 2; mf++) {
                const int r = wm * 32 + mf * 16;
                aL[mf] = *reinterpret_cast<const uint2*>(&Xc[(r + g    ) * GTS + ko]);
                aH[mf] = *reinterpret_cast<const uint2*>(&Xc[(r + g + 8) * GTS + ko]);
            }
#pragma unroll
            for (int nf = 0; nf < 8; nf++) {
                const uint2 bb =
                    *reinterpret_cast<const uint2*>(&Wc[(wn * 64 + nf * 8 + g) * GTS + ko]);
#pragma unroll
                for (int mf = 0; mf < 2; mf++)
                    mma_f16(acc[mf][nf], aL[mf].x, aH[mf].x, aL[mf].y, aH[mf].y,
                            bb.x, bb.y);
            }
        }
    }

    // Epilogue
#pragma unroll
    for (int mf = 0; mf < 2; mf++) {
        const int m = m0 + wm * 32 + mf * 16 + g;
#pragma unroll
        for (int nf = 0; nf < 8; nf++) {
            const int n = n0 + wn * 64 + nf * 8 + 2 * t;
            const float v0 = acc[mf][nf][0] + bias[n];
            const float v1 = acc[mf][nf][1] + bias[n + 1];
            const float v2 = acc[mf][nf][2] + bias[n];
            const float v3 = acc[mf][nf][3] + bias[n + 1];
            if (MODE == 0) {
                float* Y = (float*)Yv;
                *reinterpret_cast<float2*>(&Y[(size_t)m * DM + n]) = make_float2(v0, v1);
                *reinterpret_cast<float2*>(&Y[(size_t)(m + 8) * DM + n]) = make_float2(v2, v3);
            } else if (MODE == 1) {
                __half* Y = (__half*)Yv;
                const int nb_ = n0 + wn * 64 + nf * 8;
                const int h_  = nb_ >> 6;
                const int pos = ((nf >> 1) << 4) + 4 * t + ((nf & 1) << 1);  // perm pos
                const int b0_ = m / SEQ, t0_ = m % SEQ;
                const int b1_ = (m + 8) / SEQ, t1_ = (m + 8) % SEQ;
                __half* y0 = &Y[(((size_t)b0_ * HEADS + h_) * SEQ + t0_) * DK];
                __half* y1 = &Y[(((size_t)b1_ * HEADS + h_) * SEQ + t1_) * DK];
                *reinterpret_cast<uint32_t*>(&y0[pos]) = f2h2(v0 * scl, v1 * scl);
                *reinterpret_cast<uint32_t*>(&y1[pos]) = f2h2(v2 * scl, v3 * scl);
            } else {   // MODE 2: V transposed [B,H,dk,T]
                __half* Y = (__half*)Yv;
                const int h_ = n >> 6;
                const int d0 = n & 63, d1 = d0 + 1;
                const int b0_ = m / SEQ, t0_ = m % SEQ;
                const int b1_ = (m + 8) / SEQ, t1_ = (m + 8) % SEQ;
                const size_t hb0 = ((size_t)b0_ * HEADS + h_) * DK;
                const size_t hb1 = ((size_t)b1_ * HEADS + h_) * DK;
                Y[(hb0 + d0) * SEQ + t0_] = __float2half_rn(v0);
                Y[(hb0 + d1) * SEQ + t0_] = __float2half_rn(v1);
                Y[(hb1 + d0) * SEQ + t1_] = __float2half_rn(v2);
                Y[(hb1 + d1) * SEQ + t1_] = __float2half_rn(v3);
            }
        }
    }
}

__global__ __launch_bounds__(256, 2)
void gemm_qkv_kernel(const float* __restrict__ bq,
                     const float* __restrict__ bk,
                     const float* __restrict__ bv)
{
    const int z = blockIdx.z;
    const __half* W = g_Wall + (size_t)z * DM * DM;
    const float qscale = 0.125f * 1.4426950408889634f;   // 1/sqrt(dk)*log2(e)
    if (z == 0)      gemm_body<1>(g_X, W, bq, g_Q, qscale);
    else if (z == 1) gemm_body<1>(g_X, W, bk, g_K, 1.f);
    else             gemm_body<2>(g_X, W, bv, g_V, 1.f);
}

__global__ __launch_bounds__(256, 2)
void gemm_out_kernel(const float* __restrict__ bo, float* __restrict__ Y)
{
    gemm_body<0>(g_ctx, g_Wall + (size_t)3 * DM * DM, bo, Y, 1.f);
}

// ---------------------------------------------------------------------------
// Flash attention, fp16 mma m16n8k16.
// Q/K dk-permuted halves (Q pre-scaled); V transposed [dk][T] natural.
// Block = (b,h,128 q-rows), 8 warps x 16 rows. BKV=64, cp.async dbl buffer.
// P converts straight from S accumulators to A fragments (no smem/shuffles).
// ---------------------------------------------------------------------------
#define QST 80
#define KST 80
#define VST 72
#define BKV 64
#define ATTN_SMEM_HALFS (128 * QST + 2 * BKV * KST + 2 * DK * VST)   // 29696

__global__ __launch_bounds__(256, 2)
void attn_f16_kernel()
{
    extern __shared__ __half smh[];
    __half* Qs = smh;                        // [128][QST]
    __half* Ks = Qs + 128 * QST;             // [2][BKV][KST]
    __half* Vs = Ks + 2 * BKV * KST;         // [2][DK][VST]  (rows = dk)

    const int tid  = threadIdx.x;
    const int warp = tid >> 5, lane = tid & 31;
    const int g = lane >> 2, t = lane & 3;
    const int qb = blockIdx.x;
    const int h  = blockIdx.y;
    const int b  = blockIdx.z;

    const size_t head_qk = ((size_t)b * HEADS + h) * SEQ * DK;
    const __half* Qg = g_Q + head_qk + (size_t)qb * 128 * DK;
    const __half* Kg = g_K + head_qk;
    const __half* Vg = g_V + ((size_t)b * HEADS + h) * DK * SEQ;   // [dk][T]

    // stage Q (1024 chunks) + KV tile 0 (512 + 512)
#pragma unroll
    for (int i = 0; i < 4; i++) {
        const int idx = tid + i * 256;
        const int row = idx >> 3, c8 = (idx & 7) << 3;
        cp16h(&Qs[row * QST + c8], &Qg[(size_t)row * DK + c8]);
    }
#pragma unroll
    for (int i = 0; i < 2; i++) {
        const int idx = tid + i * 256;
        const int row = idx >> 3, c8 = (idx & 7) << 3;
        cp16h(&Ks[row * KST + c8], &Kg[(size_t)row * DK + c8]);
        cp16h(&Vs[row * VST + c8], &Vg[(size_t)row * SEQ + c8]);
    }
    cp_commit();

    float O[8][4];
#pragma unroll
    for (int nf = 0; nf < 8; nf++)
#pragma unroll
        for (int j = 0; j < 4; j++) O[nf][j] = 0.f;
    float mrow0 = -INFINITY, mrow1 = -INFINITY;
    float lrow0 = 0.f, lrow1 = 0.f;

    const int qrow = warp * 16;
    const int NT = SEQ / BKV;   // 32

    for (int it = 0; it < NT; it++) {
        const int cur = it & 1;
        cp_wait<0>();
        __syncthreads();

        if (it + 1 < NT) {
            const int kb = (it + 1) * BKV;
            const int nb = (it + 1) & 1;
#pragma unroll
            for (int i = 0; i < 2; i++) {
                const int idx = tid + i * 256;
                const int row = idx >> 3, c8 = (idx & 7) << 3;
                cp16h(&Ks[nb * BKV * KST + row * KST + c8],
                      &Kg[(size_t)(kb + row) * DK + c8]);
                cp16h(&Vs[nb * DK * VST + row * VST + c8],
                      &Vg[(size_t)row * SEQ + kb + c8]);
            }
            cp_commit();
        }

        const __half* Kc = Ks + cur * BKV * KST;
        const __half* Vc = Vs + cur * DK * VST;

        // S = Q @ K^T  (k = dk 64, n = kv 64) -> s[8][4]
        float s[8][4];
#pragma unroll
        for (int nf = 0; nf < 8; nf++)
#pragma unroll
            for (int j = 0; j < 4; j++) s[nf][j] = 0.f;

#pragma unroll
        for (int kk = 0; kk < 4; kk++) {
            const int ko = kk * 16 + 4 * t;
            const uint2 aL = *reinterpret_cast<const uint2*>(&Qs[(qrow + g    ) * QST + ko]);
            const uint2 aH = *reinterpret_cast<const uint2*>(&Qs[(qrow + g + 8) * QST + ko]);
#pragma unroll
            for (int nf = 0; nf < 8; nf++) {
                const uint2 bb =
                    *reinterpret_cast<const uint2*>(&Kc[(nf * 8 + g) * KST + ko]);
                mma_f16(s[nf], aL.x, aH.x, aL.y, aH.y, bb.x, bb.y);
            }
        }

        // online softmax (rows qrow+g, qrow+g+8); S already has log2e folded
        float ml0 = -INFINITY, ml1 = -INFINITY;
#pragma unroll
        for (int nf = 0; nf < 8; nf++) {
            ml0 = fmaxf(ml0, fmaxf(s[nf][0], s[nf][1]));
            ml1 = fmaxf(ml1, fmaxf(s[nf][2], s[nf][3]));
        }
        ml0 = fmaxf(ml0, __shfl_xor_sync(0xffffffffu, ml0, 1));
        ml0 = fmaxf(ml0, __shfl_xor_sync(0xffffffffu, ml0, 2));
        ml1 = fmaxf(ml1, __shfl_xor_sync(0xffffffffu, ml1, 1));
        ml1 = fmaxf(ml1, __shfl_xor_sync(0xffffffffu, ml1, 2));
        const float mn0 = fmaxf(mrow0, ml0);
        const float mn1 = fmaxf(mrow1, ml1);
        const float alpha0 = ex2f_(mrow0 - mn0);
        const float alpha1 = ex2f_(mrow1 - mn1);

        float rs0 = 0.f, rs1 = 0.f;
        uint32_t ph[16];   // P as half2 A-frag words: [nf][lo(g)/hi(g+8)]
#pragma unroll
        for (int nf = 0; nf < 8; nf++) {
            const float p0 = ex2f_(s[nf][0] - mn0);
            const float p1 = ex2f_(s[nf][1] - mn0);
            const float p2 = ex2f_(s[nf][2] - mn1);
            const float p3 = ex2f_(s[nf][3] - mn1);
            rs0 += p0 + p1;
            rs1 += p2 + p3;
            ph[2 * nf]     = f2h2(p0, p1);
            ph[2 * nf + 1] = f2h2(p2, p3);
        }
        rs0 += __shfl_xor_sync(0xffffffffu, rs0, 1);
        rs0 += __shfl_xor_sync(0xffffffffu, rs0, 2);
        rs1 += __shfl_xor_sync(0xffffffffu, rs1, 1);
        rs1 += __shfl_xor_sync(0xffffffffu, rs1, 2);

        if (__any_sync(0xffffffffu, (alpha0 < 1.f) | (alpha1 < 1.f))) {
#pragma unroll
            for (int nf = 0; nf < 8; nf++) {
                O[nf][0] *= alpha0; O[nf][1] *= alpha0;
                O[nf][2] *= alpha1; O[nf][3] *= alpha1;
            }
        }
        lrow0 = lrow0 * alpha0 + rs0;
        lrow1 = lrow1 * alpha1 + rs1;
        mrow0 = mn0; mrow1 = mn1;

        // O += P @ V : A frags direct from ph; B from transposed V tile
#pragma unroll
        for (int kk = 0; kk < 4; kk++) {           // kv 16 per step
            const uint32_t a0 = ph[4 * kk];        // (g,   2t..): tile 2kk
            const uint32_t a1 = ph[4 * kk + 1];    // (g+8, 2t..)
            const uint32_t a2 = ph[4 * kk + 2];    // (g,   2t+8..): tile 2kk+1
            const uint32_t a3 = ph[4 * kk + 3];
            const int kvo = kk * 16 + 2 * t;
#pragma unroll
            for (int nf = 0; nf < 8; nf++) {
                const __half* vrow = &Vc[(nf * 8 + g) * VST + kvo];
                const uint32_t b0 = *reinterpret_cast<const uint32_t*>(vrow);
                const uint32_t b1 = *reinterpret_cast<const uint32_t*>(vrow + 8);
                mma_f16(O[nf], a0, a1, a2, a3, b0, b1);
            }
        }
    }

    // Epilogue: normalize, write ctx half, feature-permuted (matches Wo).
    const float inv0 = 1.f / lrow0;
    const float inv1 = 1.f / lrow1;
    const int t0 = qb * 128 + qrow + g;
#pragma unroll
    for (int nf = 0; nf < 8; nf++) {
        const int g16 = h * DK + ((nf >> 1) << 4);
        const int pos = g16 + 4 * t + ((nf & 1) << 1);
        __half* r0 = &g_ctx[((size_t)b * SEQ + t0    ) * DM];
        __half* r1 = &g_ctx[((size_t)b * SEQ + t0 + 8) * DM];
        *reinterpret_cast<uint32_t*>(&r0[pos]) = f2h2(O[nf][0] * inv0, O[nf][1] * inv0);
        *reinterpret_cast<uint32_t*>(&r1[pos]) = f2h2(O[nf][2] * inv1, O[nf][3] * inv1);
    }
}

// ---------------------------------------------------------------------------
// Launch. Inputs: x, W_q, b_q, W_k, b_k, W_v, b_v, W_out, b_out
// ---------------------------------------------------------------------------
extern "C" void kernel_launch(void* const* d_in, const int* in_sizes, int n_in,
                              void* d_out, int out_size)
{
    const float* b_q = (const float*)d_in[2];
    const float* b_k = (const float*)d_in[4];
    const float* b_v = (const float*)d_in[6];
    const float* b_o = (const float*)d_in[8];

    const int attn_smem = ATTN_SMEM_HALFS * sizeof(__half);   // 59392
    cudaFuncSetAttribute(gemm_qkv_kernel,
                         cudaFuncAttributeMaxDynamicSharedMemorySize, GEMM_SMEM_BYTES);
    cudaFuncSetAttribute(gemm_out_kernel,
                         cudaFuncAttributeMaxDynamicSharedMemorySize, GEMM_SMEM_BYTES);
    cudaFuncSetAttribute(attn_f16_kernel,
                         cudaFuncAttributeMaxDynamicSharedMemorySize, attn_smem);

    prepass_kernel<<<(MROWS * DM / 16 + 255) / 256, 256>>>(
        (const float4*)d_in[0], (const float4*)d_in[1], (const float4*)d_in[3],
        (const float4*)d_in[5], (const float4*)d_in[7]);

    gemm_qkv_kernel<<<dim3(DM / 128, MROWS / 128, 3), 256, GEMM_SMEM_BYTES>>>(
        b_q, b_k, b_v);

    attn_f16_kernel<<<dim3(SEQ / 128, HEADS, BATCH), 256, attn_smem>>>();

    gemm_out_kernel<<<dim3(DM / 128, MROWS / 128, 1), 256, GEMM_SMEM_BYTES>>>(
        b_o, (float*)d_out);
}

// round 7
// speedup vs baseline: 7.6170x; 1.0082x over previous
#include <cuda_runtime.h>
#include <cuda_fp16.h>
#include <math.h>
#include <stdint.h>

// Problem constants
#define BATCH 2
#define SEQ   2048
#define HEADS 16
#define DK    64
#define DM    1024
#define MROWS (BATCH * SEQ)   // 4096

// Scratch (device globals — no allocation allowed).
// All half tensors keep the contraction dim PERMUTED within 16-groups:
// stored order [0,1,8,9, 2,3,10,11, 4,5,12,13, 6,7,14,15], so an fp16 mma
// fragment's k-pair regs {(2t,2t+1),(2t+8,2t+9)} are 4 contiguous halves.
__device__ __half g_X[MROWS * DM];                  // k permuted
__device__ __half g_Wall[4 * DM * DM];              // k permuted
__device__ __half g_Q[BATCH * HEADS * SEQ * DK];    // dk permuted, pre-scaled
__device__ __half g_K[BATCH * HEADS * SEQ * DK];    // dk permuted
__device__ __half g_V[BATCH * HEADS * DK * SEQ];    // TRANSPOSED [B,H,dk,T]
__device__ __half g_ctx[MROWS * DM];                // feature permuted

__device__ __forceinline__ uint32_t f2h2(float a, float b) {
    __half2 h = __floats2half2_rn(a, b);
    return *reinterpret_cast<uint32_t*>(&h);
}
__device__ __forceinline__ float ex2f_(float x) {
    float y;
    asm("ex2.approx.ftz.f32 %0, %1;" : "=f"(y) : "f"(x));
    return y;
}

__device__ __forceinline__ void mma_f16(float c[4],
    uint32_t a0, uint32_t a1, uint32_t a2, uint32_t a3,
    uint32_t b0, uint32_t b1)
{
    asm volatile(
        "mma.sync.aligned.m16n8k16.row.col.f32.f16.f16.f32 "
        "{%0,%1,%2,%3}, {%4,%5,%6,%7}, {%8,%9}, {%0,%1,%2,%3};\n"
        : "+f"(c[0]), "+f"(c[1]), "+f"(c[2]), "+f"(c[3])
        : "r"(a0), "r"(a1), "r"(a2), "r"(a3), "r"(b0), "r"(b1));
}

__device__ __forceinline__ void cp16h(__half* smem_dst, const __half* gsrc) {
    uint32_t s = (uint32_t)__cvta_generic_to_shared(smem_dst);
    asm volatile("cp.async.cg.shared.global [%0], [%1], 16;\n" :: "r"(s), "l"(gsrc));
}
__device__ __forceinline__ void cp_commit() {
    asm volatile("cp.async.commit_group;\n");
}
template <int N>
__device__ __forceinline__ void cp_wait() {
    asm volatile("cp.async.wait_group %0;\n" :: "n"(N));
}

// ---------------------------------------------------------------------------
// Prepass: fp32 -> fp16 with 16-group k-permutation.
// ---------------------------------------------------------------------------
__device__ __forceinline__ void perm16(const float4* __restrict__ src,
                                       uint32_t* __restrict__ dst)
{
    const float4 v0 = src[0], v1 = src[1], v2 = src[2], v3 = src[3];
    dst[0] = f2h2(v0.x, v0.y);  dst[1] = f2h2(v2.x, v2.y);
    dst[2] = f2h2(v0.z, v0.w);  dst[3] = f2h2(v2.z, v2.w);
    dst[4] = f2h2(v1.x, v1.y);  dst[5] = f2h2(v3.x, v3.y);
    dst[6] = f2h2(v1.z, v1.w);  dst[7] = f2h2(v3.z, v3.w);
}

__global__ void prepass_kernel(const float4* __restrict__ x,
                               const float4* __restrict__ wq,
                               const float4* __restrict__ wk,
                               const float4* __restrict__ wv,
                               const float4* __restrict__ wo)
{
    const int i = blockIdx.x * blockDim.x + threadIdx.x;
    uint32_t* X2 = reinterpret_cast<uint32_t*>(g_X);
    uint32_t* W2 = reinterpret_cast<uint32_t*>(g_Wall);
    if (i < MROWS * DM / 16)
        perm16(&x[4 * i], &X2[8 * i]);
    if (i < DM * DM / 16) {
        const int WQ = DM * DM / 2;
        perm16(&wq[4 * i], &W2[8 * i]);
        perm16(&wk[4 * i], &W2[8 * i + WQ]);
        perm16(&wv[4 * i], &W2[8 * i + 2 * WQ]);
        perm16(&wo[4 * i], &W2[8 * i + 3 * WQ]);
    }
}

// ---------------------------------------------------------------------------
// fp16 GEMM, 4-stage cp.async pipeline. Y = X @ W^T + bias.
// 128x128 CTA tile, BK=32 chunks (32 of them), 8 warps 4(M)x2(N),
// warp tile 32x64, m16n8k16. Stage = X(128x48) + W(128x48) halves = 24KB.
// GTS=48 (96B row): LDS.64 fragment phases hit distinct banks.
// MODE 0: fp32 [M,N].  MODE 1: half scatter [B,H,T,dk] dk-perm (scaled).
// MODE 2: half scatter TRANSPOSED [B,H,dk,T].
// ---------------------------------------------------------------------------
#define GTS 48
#define G_TILE (128 * GTS)                    // halves per tile per stage
#define GEMM_SMEM_BYTES (4 * 2 * G_TILE * 2)  // 98304
#define NKB32 (DM / 32)                       // 32

template <int MODE>
__device__ __forceinline__ void gemm_body(const __half* __restrict__ X,
                                          const __half* __restrict__ W,
                                          const float* __restrict__ bias,
                                          void* __restrict__ Yv,
                                          float scl)
{
    extern __shared__ __half smh[];

    const int tid  = threadIdx.x;
    const int warp = tid >> 5, lane = tid & 31;
    const int g = lane >> 2, t = lane & 3;
    const int wm = warp >> 1;
    const int wn = warp & 1;
    const int m0 = blockIdx.y * 128;
    const int n0 = blockIdx.x * 128;

    // loader coords: 2 chunks per tile per thread (rows lr, lr+64)
    const int lr = tid >> 2;            // 0..63
    const int lc = (tid & 3) * 8;       // 0,8,16,24 halves

    auto stage_load = [&](int kb) {
        __half* Xs = smh + (kb & 3) * (2 * G_TILE);
        __half* Ws = Xs + G_TILE;
        const int k0 = kb * 32;
        cp16h(&Xs[lr * GTS + lc],        &X[(size_t)(m0 + lr     ) * DM + k0 + lc]);
        cp16h(&Xs[(lr + 64) * GTS + lc], &X[(size_t)(m0 + lr + 64) * DM + k0 + lc]);
        cp16h(&Ws[lr * GTS + lc],        &W[(size_t)(n0 + lr     ) * DM + k0 + lc]);
        cp16h(&Ws[(lr + 64) * GTS + lc], &W[(size_t)(n0 + lr + 64) * DM + k0 + lc]);
    };

    stage_load(0); cp_commit();
    stage_load(1); cp_commit();
    stage_load(2); cp_commit();

    float acc[2][8][4] = {};

    const int aoff = (wm * 32 + g) * GTS + 4 * t;
    const int boff = (wn * 64 + g) * GTS + 4 * t;

#pragma unroll 4
    for (int kb = 0; kb < NKB32; kb++) {
        cp_wait<2>();        // with one commit per iter: stage kb is resident
        __syncthreads();     // and all warps are done with the stage we reuse

        if (kb + 3 < NKB32) stage_load(kb + 3);
        cp_commit();         // unconditional: keeps group accounting exact

        const __half* Xc = smh + (kb & 3) * (2 * G_TILE);
        const __half* Wc = Xc + G_TILE;
#pragma unroll
        for (int kk = 0; kk < 2; kk++) {
            const int ko = kk * 16;
            uint2 aL[2], aH[2];
#pragma unroll
            for (int mf = 0; mf < 2; mf++) {
                aL[mf] = *reinterpret_cast<const uint2*>(Xc + aoff + mf * 16 * GTS + ko);
                aH[mf] = *reinterpret_cast<const uint2*>(Xc + aoff + mf * 16 * GTS + 8 * GTS + ko);
            }
#pragma unroll
            for (int nf = 0; nf < 8; nf++) {
                const uint2 bb =
                    *reinterpret_cast<const uint2*>(Wc + boff + nf * 8 * GTS + ko);
#pragma unroll
                for (int mf = 0; mf < 2; mf++)
                    mma_f16(acc[mf][nf], aL[mf].x, aH[mf].x, aL[mf].y, aH[mf].y,
                            bb.x, bb.y);
            }
        }
    }

    // Epilogue (identical layouts to R6)
#pragma unroll
    for (int mf = 0; mf < 2; mf++) {
        const int m = m0 + wm * 32 + mf * 16 + g;
#pragma unroll
        for (int nf = 0; nf < 8; nf++) {
            const int n = n0 + wn * 64 + nf * 8 + 2 * t;
            const float v0 = acc[mf][nf][0] + bias[n];
            const float v1 = acc[mf][nf][1] + bias[n + 1];
            const float v2 = acc[mf][nf][2] + bias[n];
            const float v3 = acc[mf][nf][3] + bias[n + 1];
            if (MODE == 0) {
                float* Y = (float*)Yv;
                *reinterpret_cast<float2*>(&Y[(size_t)m * DM + n]) = make_float2(v0, v1);
                *reinterpret_cast<float2*>(&Y[(size_t)(m + 8) * DM + n]) = make_float2(v2, v3);
            } else if (MODE == 1) {
                __half* Y = (__half*)Yv;
                const int nb_ = n0 + wn * 64 + nf * 8;
                const int h_  = nb_ >> 6;
                const int pos = ((nf >> 1) << 4) + 4 * t + ((nf & 1) << 1);
                const int b0_ = m / SEQ, t0_ = m % SEQ;
                const int b1_ = (m + 8) / SEQ, t1_ = (m + 8) % SEQ;
                __half* y0 = &Y[(((size_t)b0_ * HEADS + h_) * SEQ + t0_) * DK];
                __half* y1 = &Y[(((size_t)b1_ * HEADS + h_) * SEQ + t1_) * DK];
                *reinterpret_cast<uint32_t*>(&y0[pos]) = f2h2(v0 * scl, v1 * scl);
                *reinterpret_cast<uint32_t*>(&y1[pos]) = f2h2(v2 * scl, v3 * scl);
            } else {
                __half* Y = (__half*)Yv;
                const int h_ = n >> 6;
                const int d0 = n & 63, d1 = d0 + 1;
                const int b0_ = m / SEQ, t0_ = m % SEQ;
                const int b1_ = (m + 8) / SEQ, t1_ = (m + 8) % SEQ;
                const size_t hb0 = ((size_t)b0_ * HEADS + h_) * DK;
                const size_t hb1 = ((size_t)b1_ * HEADS + h_) * DK;
                Y[(hb0 + d0) * SEQ + t0_] = __float2half_rn(v0);
                Y[(hb0 + d1) * SEQ + t0_] = __float2half_rn(v1);
                Y[(hb1 + d0) * SEQ + t1_] = __float2half_rn(v2);
                Y[(hb1 + d1) * SEQ + t1_] = __float2half_rn(v3);
            }
        }
    }
}

__global__ __launch_bounds__(256, 2)
void gemm_qkv_kernel(const float* __restrict__ bq,
                     const float* __restrict__ bk,
                     const float* __restrict__ bv)
{
    const int z = blockIdx.z;
    const __half* W = g_Wall + (size_t)z * DM * DM;
    const float qscale = 0.125f * 1.4426950408889634f;
    if (z == 0)      gemm_body<1>(g_X, W, bq, g_Q, qscale);
    else if (z == 1) gemm_body<1>(g_X, W, bk, g_K, 1.f);
    else             gemm_body<2>(g_X, W, bv, g_V, 1.f);
}

__global__ __launch_bounds__(256, 2)
void gemm_out_kernel(const float* __restrict__ bo, float* __restrict__ Y)
{
    gemm_body<0>(g_ctx, g_Wall + (size_t)3 * DM * DM, bo, Y, 1.f);
}

// ---------------------------------------------------------------------------
// Flash attention, fp16 mma, 4-stage KV pipeline (BKV=64).
// Q/K dk-permuted (Q pre-scaled by 1/sqrt(dk)*log2e); V transposed [dk][T].
// P converts directly from S accumulators into A fragments (no smem traffic).
// ---------------------------------------------------------------------------
#define QST 80
#define KST 80
#define VST 72
#define BKV 64
#define Q_HALFS (128 * QST)
#define A_STAGE (BKV * KST + DK * VST)                     // 9728
#define ATTN_SMEM_BYTES ((Q_HALFS + 4 * A_STAGE) * 2)      // 98304

__global__ __launch_bounds__(256, 2)
void attn_f16_kernel()
{
    extern __shared__ __half smh[];
    __half* Qs = smh;   // [128][QST], then 4 stages of {K[64][KST], V[64][VST]}

    const int tid  = threadIdx.x;
    const int warp = tid >> 5, lane = tid & 31;
    const int g = lane >> 2, t = lane & 3;
    const int qb = blockIdx.x;
    const int h  = blockIdx.y;
    const int b  = blockIdx.z;

    const size_t head_qk = ((size_t)b * HEADS + h) * SEQ * DK;
    const __half* Qg = g_Q + head_qk + (size_t)qb * 128 * DK;
    const __half* Kg = g_K + head_qk;
    const __half* Vg = g_V + ((size_t)b * HEADS + h) * DK * SEQ;

    const int lr = tid >> 3;            // 0..31
    const int lc = (tid & 7) * 8;       // 0..56 halves

    auto stage_load = [&](int it) {
        __half* Ks = smh + Q_HALFS + (it & 3) * A_STAGE;
        __half* Vs = Ks + BKV * KST;
        const int kb = it * BKV;
        cp16h(&Ks[lr * KST + lc],        &Kg[(size_t)(kb + lr     ) * DK + lc]);
        cp16h(&Ks[(lr + 32) * KST + lc], &Kg[(size_t)(kb + lr + 32) * DK + lc]);
        cp16h(&Vs[lr * VST + lc],        &Vg[(size_t)(lr     ) * SEQ + kb + lc]);
        cp16h(&Vs[(lr + 32) * VST + lc], &Vg[(size_t)(lr + 32) * SEQ + kb + lc]);
    };

    // prologue: Q + stage 0 in group 0; stages 1,2 in groups 1,2
#pragma unroll
    for (int i = 0; i < 4; i++) {
        const int row = lr + i * 32;
        cp16h(&Qs[row * QST + lc], &Qg[(size_t)row * DK + lc]);
    }
    stage_load(0); cp_commit();
    stage_load(1); cp_commit();
    stage_load(2); cp_commit();

    float O[8][4] = {};
    float mrow0 = -INFINITY, mrow1 = -INFINITY;
    float lrow0 = 0.f, lrow1 = 0.f;

    const int qrow = warp * 16;
    const int qoff = (qrow + g) * QST + 4 * t;
    const int koff = g * KST + 4 * t;
    const int voff = g * VST + 2 * t;
    const int NT = SEQ / BKV;   // 32

    for (int it = 0; it < NT; it++) {
        cp_wait<2>();
        __syncthreads();

        if (it + 3 < NT) stage_load(it + 3);
        cp_commit();

        const __half* Kc = smh + Q_HALFS + (it & 3) * A_STAGE;
        const __half* Vc = Kc + BKV * KST;

        // S = Q @ K^T -> s[8][4]
        float s[8][4] = {};
#pragma unroll
        for (int kk = 0; kk < 4; kk++) {
            const int ko = kk * 16;
            const uint2 aL = *reinterpret_cast<const uint2*>(Qs + qoff + ko);
            const uint2 aH = *reinterpret_cast<const uint2*>(Qs + qoff + 8 * QST + ko);
#pragma unroll
            for (int nf = 0; nf < 8; nf++) {
                const uint2 bb =
                    *reinterpret_cast<const uint2*>(Kc + koff + nf * 8 * KST + ko);
                mma_f16(s[nf], aL.x, aH.x, aL.y, aH.y, bb.x, bb.y);
            }
        }

        // online softmax (rows qrow+g, qrow+g+8); log2e pre-folded into Q
        float ml0 = -INFINITY, ml1 = -INFINITY;
#pragma unroll
        for (int nf = 0; nf < 8; nf++) {
            ml0 = fmaxf(ml0, fmaxf(s[nf][0], s[nf][1]));
            ml1 = fmaxf(ml1, fmaxf(s[nf][2], s[nf][3]));
        }
        ml0 = fmaxf(ml0, __shfl_xor_sync(0xffffffffu, ml0, 1));
        ml0 = fmaxf(ml0, __shfl_xor_sync(0xffffffffu, ml0, 2));
        ml1 = fmaxf(ml1, __shfl_xor_sync(0xffffffffu, ml1, 1));
        ml1 = fmaxf(ml1, __shfl_xor_sync(0xffffffffu, ml1, 2));
        const float mn0 = fmaxf(mrow0, ml0);
        const float mn1 = fmaxf(mrow1, ml1);
        const float alpha0 = ex2f_(mrow0 - mn0);
        const float alpha1 = ex2f_(mrow1 - mn1);

        float rs0 = 0.f, rs1 = 0.f;
        uint32_t ph[16];
#pragma unroll
        for (int nf = 0; nf < 8; nf++) {
            const float p0 = ex2f_(s[nf][0] - mn0);
            const float p1 = ex2f_(s[nf][1] - mn0);
            const float p2 = ex2f_(s[nf][2] - mn1);
            const float p3 = ex2f_(s[nf][3] - mn1);
            rs0 += p0 + p1;
            rs1 += p2 + p3;
            ph[2 * nf]     = f2h2(p0, p1);
            ph[2 * nf + 1] = f2h2(p2, p3);
        }
        rs0 += __shfl_xor_sync(0xffffffffu, rs0, 1);
        rs0 += __shfl_xor_sync(0xffffffffu, rs0, 2);
        rs1 += __shfl_xor_sync(0xffffffffu, rs1, 1);
        rs1 += __shfl_xor_sync(0xffffffffu, rs1, 2);

        if (__any_sync(0xffffffffu, (alpha0 < 1.f) | (alpha1 < 1.f))) {
#pragma unroll
            for (int nf = 0; nf < 8; nf++) {
                O[nf][0] *= alpha0; O[nf][1] *= alpha0;
                O[nf][2] *= alpha1; O[nf][3] *= alpha1;
            }
        }
        lrow0 = lrow0 * alpha0 + rs0;
        lrow1 = lrow1 * alpha1 + rs1;
        mrow0 = mn0; mrow1 = mn1;

        // O += P @ V
#pragma unroll
        for (int kk = 0; kk < 4; kk++) {
            const uint32_t a0 = ph[4 * kk];
            const uint32_t a1 = ph[4 * kk + 1];
            const uint32_t a2 = ph[4 * kk + 2];
            const uint32_t a3 = ph[4 * kk + 3];
            const int kvo = kk * 16;
#pragma unroll
            for (int nf = 0; nf < 8; nf++) {
                const __half* vrow = Vc + voff + nf * 8 * VST + kvo;
                const uint32_t b0 = *reinterpret_cast<const uint32_t*>(vrow);
                const uint32_t b1 = *reinterpret_cast<const uint32_t*>(vrow + 8);
                mma_f16(O[nf], a0, a1, a2, a3, b0, b1);
            }
        }
    }

    // Epilogue: normalize, write ctx half, feature-permuted (matches Wo).
    const float inv0 = 1.f / lrow0;
    const float inv1 = 1.f / lrow1;
    const int t0 = qb * 128 + qrow + g;
#pragma unroll
    for (int nf = 0; nf < 8; nf++) {
        const int g16 = h * DK + ((nf >> 1) << 4);
        const int pos = g16 + 4 * t + ((nf & 1) << 1);
        __half* r0 = &g_ctx[((size_t)b * SEQ + t0    ) * DM];
        __half* r1 = &g_ctx[((size_t)b * SEQ + t0 + 8) * DM];
        *reinterpret_cast<uint32_t*>(&r0[pos]) = f2h2(O[nf][0] * inv0, O[nf][1] * inv0);
        *reinterpret_cast<uint32_t*>(&r1[pos]) = f2h2(O[nf][2] * inv1, O[nf][3] * inv1);
    }
}

// ---------------------------------------------------------------------------
// Launch. Inputs: x, W_q, b_q, W_k, b_k, W_v, b_v, W_out, b_out
// ---------------------------------------------------------------------------
extern "C" void kernel_launch(void* const* d_in, const int* in_sizes, int n_in,
                              void* d_out, int out_size)
{
    const float* b_q = (const float*)d_in[2];
    const float* b_k = (const float*)d_in[4];
    const float* b_v = (const float*)d_in[6];
    const float* b_o = (const float*)d_in[8];

    cudaFuncSetAttribute(gemm_qkv_kernel,
                         cudaFuncAttributeMaxDynamicSharedMemorySize, GEMM_SMEM_BYTES);
    cudaFuncSetAttribute(gemm_out_kernel,
                         cudaFuncAttributeMaxDynamicSharedMemorySize, GEMM_SMEM_BYTES);
    cudaFuncSetAttribute(attn_f16_kernel,
                         cudaFuncAttributeMaxDynamicSharedMemorySize, ATTN_SMEM_BYTES);

    prepass_kernel<<<(MROWS * DM / 16 + 255) / 256, 256>>>(
        (const float4*)d_in[0], (const float4*)d_in[1], (const float4*)d_in[3],
        (const float4*)d_in[5], (const float4*)d_in[7]);

    gemm_qkv_kernel<<<dim3(DM / 128, MROWS / 128, 3), 256, GEMM_SMEM_BYTES>>>(
        b_q, b_k, b_v);

    attn_f16_kernel<<<dim3(SEQ / 128, HEADS, BATCH), 256, ATTN_SMEM_BYTES>>>();

    gemm_out_kernel<<<dim3(DM / 128, MROWS / 128, 1), 256, GEMM_SMEM_BYTES>>>(
        b_o, (float*)d_out);
}